// round 1
// baseline (speedup 1.0000x reference)
#include <cuda_runtime.h>
#include <math.h>

#define N_NODES 50000
#define N_EDGES 800000
#define HDIM    128
#define NGRAPH  64
#define NEG     0.01f

static const long NHF = 6400000L; // N_NODES * HDIM

// Scratch layout (floats):
//   [0*NHF) XW/tmp   [1*NHF) H   [2*NHF) G   [3*NHF) M
//   [4*NHF) GI (3*NHF)           [7*NHF) GH (3*NHF)   total 10*NHF = 256 MB
__device__ __align__(256) float d_scratch[64000000L];
__device__ float d_dinv[N_NODES];
__device__ float d_probs[N_NODES];
__device__ int d_degc[N_NODES];
__device__ int d_degr[N_NODES];
__device__ int d_fill[N_NODES];
__device__ int d_off[N_NODES + 1];
__device__ int d_csr[N_EDGES];

__device__ __forceinline__ float leaky(float x) { return x > 0.f ? x : NEG * x; }
__device__ __forceinline__ float sigm(float x)  { return 1.f / (1.f + __expf(-x)); }

// ---------------------------------------------------------------- CSR build

__global__ void k_zero(float* out) {
    int i = blockIdx.x * blockDim.x + threadIdx.x;
    if (i < N_NODES) { d_degc[i] = 0; d_degr[i] = 0; d_fill[i] = 0; }
    if (i < NGRAPH) out[i] = 0.f;
}

__global__ void k_count(const int* __restrict__ row, const int* __restrict__ col) {
    int e = blockIdx.x * blockDim.x + threadIdx.x;
    if (e < N_EDGES) {
        atomicAdd(&d_degc[col[e]], 1);
        atomicAdd(&d_degr[row[e]], 1);
    }
}

__global__ void k_dinv() {
    int i = blockIdx.x * blockDim.x + threadIdx.x;
    if (i < N_NODES) d_dinv[i] = rsqrtf((float)d_degc[i] + 1.f);
}

__global__ void k_scan() {
    __shared__ int sm[1024];
    __shared__ int carry;
    int t = threadIdx.x;
    if (t == 0) carry = 0;
    __syncthreads();
    for (int base = 0; base < N_NODES; base += 1024) {
        int i = base + t;
        int v = (i < N_NODES) ? d_degc[i] : 0;
        sm[t] = v;
        __syncthreads();
        for (int o = 1; o < 1024; o <<= 1) {
            int x = (t >= o) ? sm[t - o] : 0;
            __syncthreads();
            sm[t] += x;
            __syncthreads();
        }
        if (i < N_NODES) d_off[i] = carry + sm[t] - v;
        __syncthreads();
        if (t == 0) carry += sm[1023];
        __syncthreads();
    }
    if (t == 0) d_off[N_NODES] = carry;
}

__global__ void k_scatter(const int* __restrict__ row, const int* __restrict__ col) {
    int e = blockIdx.x * blockDim.x + threadIdx.x;
    if (e < N_EDGES) {
        int c = col[e];
        int pos = d_off[c] + atomicAdd(&d_fill[c], 1);
        d_csr[pos] = row[e];
    }
}

// ---------------------------------------------------------------- GEMM (K=128)
// C[M,NC] = A[M,128] @ B, B row-major [128,NC] (TB=false) or stored [NC,128]
// with logical B[k][n] = Bstore[n][k] (TB=true). Optional bias + leaky act.

template <bool TB, int ACT>
__global__ void __launch_bounds__(256) k_gemm(
    const float* __restrict__ A, const float* __restrict__ B,
    const float* __restrict__ bias, float* __restrict__ C, int NC)
{
    __shared__ float As[32][68];   // [k][m], padded
    __shared__ float Bs[32][132];  // [k][n], padded
    int m0 = blockIdx.x * 64;
    int n0 = blockIdx.y * 128;
    int tid = threadIdx.x;
    int tx = tid & 31;   // col group: cols tx*4 .. tx*4+3
    int ty = tid >> 5;   // row group: rows ty*8 .. ty*8+7

    float acc[8][4];
#pragma unroll
    for (int i = 0; i < 8; i++)
#pragma unroll
        for (int j = 0; j < 4; j++) acc[i][j] = 0.f;

    for (int kc = 0; kc < 128; kc += 32) {
        { // A chunk: 64 rows x 32 k
            int k = tid & 31, r0 = tid >> 5;
#pragma unroll
            for (int i = 0; i < 8; i++) {
                int rr = r0 + i * 8;
                int gm = m0 + rr;
                As[k][rr] = (gm < N_NODES) ? A[(long)gm * 128 + kc + k] : 0.f;
            }
        }
        if (!TB) { // B row-major [128, NC]
            int n = tid & 127, kb = tid >> 7;
#pragma unroll
            for (int j = 0; j < 16; j++) {
                int k = kb + j * 2;
                Bs[k][n] = B[(long)(kc + k) * NC + n0 + n];
            }
        } else {   // B stored [NC, 128]; logical B[k][n] = Bst[n][k]
            int k = tid & 31, nb = tid >> 5;
#pragma unroll
            for (int j = 0; j < 16; j++) {
                int nn = nb + j * 8;
                Bs[k][nn] = B[(long)(n0 + nn) * 128 + kc + k];
            }
        }
        __syncthreads();
#pragma unroll
        for (int k = 0; k < 32; k++) {
            float4 b4 = *(const float4*)&Bs[k][tx * 4];
            float4 a0 = *(const float4*)&As[k][ty * 8];
            float4 a1 = *(const float4*)&As[k][ty * 8 + 4];
            float av[8] = {a0.x, a0.y, a0.z, a0.w, a1.x, a1.y, a1.z, a1.w};
            float bv[4] = {b4.x, b4.y, b4.z, b4.w};
#pragma unroll
            for (int i = 0; i < 8; i++)
#pragma unroll
                for (int j = 0; j < 4; j++)
                    acc[i][j] = fmaf(av[i], bv[j], acc[i][j]);
        }
        __syncthreads();
    }

    float bv[4] = {0.f, 0.f, 0.f, 0.f};
    if (bias) {
#pragma unroll
        for (int j = 0; j < 4; j++) bv[j] = bias[n0 + tx * 4 + j];
    }
#pragma unroll
    for (int i = 0; i < 8; i++) {
        int gm = m0 + ty * 8 + i;
        if (gm < N_NODES) {
            float4 o;
            o.x = acc[i][0] + bv[0];
            o.y = acc[i][1] + bv[1];
            o.z = acc[i][2] + bv[2];
            o.w = acc[i][3] + bv[3];
            if (ACT == 1) { o.x = leaky(o.x); o.y = leaky(o.y); o.z = leaky(o.z); o.w = leaky(o.w); }
            *(float4*)&C[(long)gm * NC + n0 + tx * 4] = o;
        }
    }
}

// ---------------------------------------------------------------- aggregation
// warp-per-node pull from CSR; features as float4 (lane f4 = 4 feats)

__global__ void k_gcn_agg(const float* __restrict__ xw, const float* __restrict__ bias,
                          float* __restrict__ hout, float* __restrict__ gout)
{
    int v = blockIdx.x * 8 + (threadIdx.x >> 5);
    if (v >= N_NODES) return;
    int lane = threadIdx.x & 31;
    const float4* x4 = (const float4*)xw;
    float4 acc = make_float4(0.f, 0.f, 0.f, 0.f);
    float dv = d_dinv[v];
    int s = d_off[v], e = d_off[v + 1];
    for (int i = s; i < e; i++) {
        int u = d_csr[i];
        float c = d_dinv[u] * dv;
        float4 t = x4[(long)u * 32 + lane];
        acc.x += t.x * c; acc.y += t.y * c; acc.z += t.z * c; acc.w += t.w * c;
    }
    float4 slf = x4[(long)v * 32 + lane];
    float sc = dv * dv;
    float4 b = ((const float4*)bias)[lane];
    acc.x = leaky(acc.x + slf.x * sc + b.x);
    acc.y = leaky(acc.y + slf.y * sc + b.y);
    acc.z = leaky(acc.z + slf.z * sc + b.z);
    acc.w = leaky(acc.w + slf.w * sc + b.w);
    ((float4*)hout)[(long)v * 32 + lane] = acc;
    ((float4*)gout)[(long)v * 32 + lane] = acc;
}

__global__ void k_gg_agg(const float* __restrict__ gw, float* __restrict__ mout) {
    int v = blockIdx.x * 8 + (threadIdx.x >> 5);
    if (v >= N_NODES) return;
    int lane = threadIdx.x & 31;
    const float4* x4 = (const float4*)gw;
    float4 acc = make_float4(0.f, 0.f, 0.f, 0.f);
    int s = d_off[v], e = d_off[v + 1];
    for (int i = s; i < e; i++) {
        int u = d_csr[i];
        float4 t = x4[(long)u * 32 + lane];
        acc.x += t.x; acc.y += t.y; acc.z += t.z; acc.w += t.w;
    }
    ((float4*)mout)[(long)v * 32 + lane] = acc;
}

// ---------------------------------------------------------------- elementwise

__global__ void k_gru(const float* __restrict__ gi, const float* __restrict__ gh,
                      float* __restrict__ g)
{
    long i = (long)blockIdx.x * blockDim.x + threadIdx.x;
    if (i >= NHF) return;
    int v = (int)(i >> 7);
    int f = (int)(i & 127);
    long b3 = (long)v * 384;
    float ir = gi[b3 + f], iz = gi[b3 + 128 + f], in_ = gi[b3 + 256 + f];
    float hr = gh[b3 + f], hz = gh[b3 + 128 + f], hn = gh[b3 + 256 + f];
    float r = sigm(ir + hr);
    float z = sigm(iz + hz);
    float n = tanhf(in_ + r * hn);
    float hv = g[i];
    g[i] = (1.f - z) * n + z * hv;
}

__global__ void k_resid(const float* __restrict__ g, float* __restrict__ h) {
    long i = (long)blockIdx.x * blockDim.x + threadIdx.x;
    if (i < NHF) h[i] = leaky(g[i]) + h[i];
}

__global__ void k_probs(const float* __restrict__ t, const float* __restrict__ W2,
                        const float* __restrict__ b2)
{
    int v = blockIdx.x * 8 + (threadIdx.x >> 5);
    if (v >= N_NODES) return;
    int lane = threadIdx.x & 31;
    float4 tv = ((const float4*)t)[(long)v * 32 + lane];
    float4 wv = ((const float4*)W2)[lane];
    float s = tv.x * wv.x + tv.y * wv.y + tv.z * wv.z + tv.w * wv.w;
#pragma unroll
    for (int o = 16; o; o >>= 1) s += __shfl_xor_sync(0xffffffffu, s, o);
    if (lane == 0) d_probs[v] = sigm(s + b2[0]);
}

// ---------------------------------------------------------------- loss

__global__ void k_loss_nodes(const int* __restrict__ batch, float* __restrict__ out) {
    __shared__ float sm[NGRAPH];
    if (threadIdx.x < NGRAPH) sm[threadIdx.x] = 0.f;
    __syncthreads();
    for (int v = blockIdx.x * blockDim.x + threadIdx.x; v < N_NODES;
         v += gridDim.x * blockDim.x) {
        float w = -0.5f * d_probs[v] * (float)d_degr[v];
        atomicAdd(&sm[batch[v]], w);
    }
    __syncthreads();
    if (threadIdx.x < NGRAPH) atomicAdd(&out[threadIdx.x], sm[threadIdx.x]);
}

__global__ void k_loss_edges(const int* __restrict__ row, const int* __restrict__ col,
                             const int* __restrict__ batch, float* __restrict__ out)
{
    __shared__ float sm[NGRAPH];
    if (threadIdx.x < NGRAPH) sm[threadIdx.x] = 0.f;
    __syncthreads();
    for (int e = blockIdx.x * blockDim.x + threadIdx.x; e < N_EDGES;
         e += gridDim.x * blockDim.x) {
        int r = row[e];
        float w = 0.5f * d_probs[r] * d_probs[col[e]];
        atomicAdd(&sm[batch[r]], w);
    }
    __syncthreads();
    if (threadIdx.x < NGRAPH) atomicAdd(&out[threadIdx.x], sm[threadIdx.x]);
}

// ---------------------------------------------------------------- launch

extern "C" void kernel_launch(void* const* d_in, const int* in_sizes, int n_in,
                              void* d_out, int out_size)
{
    const float* x     = (const float*)d_in[0];
    const int*   ei    = (const int*)d_in[1];
    const int*   batch = (const int*)d_in[2];
    const float* W_gcn = (const float*)d_in[3];
    const float* b_gcn = (const float*)d_in[4];
    const float* W_gg  = (const float*)d_in[5];
    const float* W_ih  = (const float*)d_in[6];
    const float* W_hh  = (const float*)d_in[7];
    const float* b_ih  = (const float*)d_in[8];
    const float* b_hh  = (const float*)d_in[9];
    const float* W1    = (const float*)d_in[10];
    const float* b1    = (const float*)d_in[11];
    const float* W2    = (const float*)d_in[12];
    const float* b2    = (const float*)d_in[13];
    float* out = (float*)d_out;
    const int* row = ei;
    const int* col = ei + N_EDGES;

    float* S = nullptr;
    cudaGetSymbolAddress((void**)&S, d_scratch);
    float* XW = S;
    float* Hb = S + 1 * NHF;
    float* Gb = S + 2 * NHF;
    float* Mb = S + 3 * NHF;
    float* GI = S + 4 * NHF;
    float* GH = S + 7 * NHF;

    // CSR build (per replay; cheap, deterministic up to fp-sum order)
    k_zero<<<196, 256>>>(out);
    k_count<<<3125, 256>>>(row, col);
    k_dinv<<<196, 256>>>();
    k_scan<<<1, 1024>>>();
    k_scatter<<<3125, 256>>>(row, col);

    dim3 g1(782, 1), g3(782, 3);

    // GCN
    k_gemm<false, 0><<<g1, 256>>>(x, W_gcn, nullptr, XW, 128);
    k_gcn_agg<<<6250, 256>>>(XW, b_gcn, Hb, Gb);

    // 3x GatedGraphConv + GRU
    for (int l = 0; l < 3; l++) {
        k_gemm<false, 0><<<g1, 256>>>(Gb, W_gg + (long)l * 128 * 128, nullptr, XW, 128);
        k_gg_agg<<<6250, 256>>>(XW, Mb);
        k_gemm<true, 0><<<g3, 256>>>(Mb, W_ih, b_ih, GI, 384);
        k_gemm<true, 0><<<g3, 256>>>(Gb, W_hh, b_hh, GH, 384);
        k_gru<<<25000, 256>>>(GI, GH, Gb);
    }

    // head
    k_resid<<<25000, 256>>>(Gb, Hb);
    k_gemm<false, 1><<<g1, 256>>>(Hb, W1, b1, XW, 128);
    k_probs<<<6250, 256>>>(XW, W2, b2);

    // loss
    k_loss_nodes<<<512, 256>>>(batch, out);
    k_loss_edges<<<512, 256>>>(row, col, batch, out);
}

// round 3
// speedup vs baseline: 1.0012x; 1.0012x over previous
#include <cuda_runtime.h>
#include <math.h>

#define N_NODES 50000
#define N_EDGES 800000
#define HDIM    128
#define NGRAPH  64
#define NEG     0.01f

static const long NHF = 6400000L; // N_NODES * HDIM

// Scratch layout (floats):
//   [0*NHF) XW/tmp   [1*NHF) H   [2*NHF) G   [3*NHF) M
//   [4*NHF) GI (3*NHF)           [7*NHF) GH (3*NHF)   total 10*NHF = 256 MB
__device__ __align__(256) float d_scratch[64000000L];
__device__ float d_dinv[N_NODES];
__device__ float d_probs[N_NODES];
__device__ int d_degc[N_NODES];
__device__ int d_degr[N_NODES];
__device__ int d_fill[N_NODES];
__device__ int d_off[N_NODES + 1];
__device__ int d_csr[N_EDGES];

__device__ __forceinline__ float leaky(float x) { return x > 0.f ? x : NEG * x; }
__device__ __forceinline__ float sigm(float x)  { return 1.f / (1.f + __expf(-x)); }

// ---------------------------------------------------------------- CSR build

__global__ void k_zero(float* out) {
    int i = blockIdx.x * blockDim.x + threadIdx.x;
    if (i < N_NODES) { d_degc[i] = 0; d_degr[i] = 0; d_fill[i] = 0; }
    if (i < NGRAPH) out[i] = 0.f;
}

__global__ void k_count(const int* __restrict__ row, const int* __restrict__ col) {
    int e = blockIdx.x * blockDim.x + threadIdx.x;
    if (e < N_EDGES) {
        atomicAdd(&d_degc[col[e]], 1);
        atomicAdd(&d_degr[row[e]], 1);
    }
}

__global__ void k_dinv() {
    int i = blockIdx.x * blockDim.x + threadIdx.x;
    if (i < N_NODES) d_dinv[i] = rsqrtf((float)d_degc[i] + 1.f);
}

__global__ void k_scan() {
    __shared__ int sm[1024];
    __shared__ int carry;
    int t = threadIdx.x;
    if (t == 0) carry = 0;
    __syncthreads();
    for (int base = 0; base < N_NODES; base += 1024) {
        int i = base + t;
        int v = (i < N_NODES) ? d_degc[i] : 0;
        sm[t] = v;
        __syncthreads();
        for (int o = 1; o < 1024; o <<= 1) {
            int x = (t >= o) ? sm[t - o] : 0;
            __syncthreads();
            sm[t] += x;
            __syncthreads();
        }
        if (i < N_NODES) d_off[i] = carry + sm[t] - v;
        __syncthreads();
        if (t == 0) carry += sm[1023];
        __syncthreads();
    }
    if (t == 0) d_off[N_NODES] = carry;
}

__global__ void k_scatter(const int* __restrict__ row, const int* __restrict__ col) {
    int e = blockIdx.x * blockDim.x + threadIdx.x;
    if (e < N_EDGES) {
        int c = col[e];
        int pos = d_off[c] + atomicAdd(&d_fill[c], 1);
        d_csr[pos] = row[e];
    }
}

// ---------------------------------------------------------------- GEMM (K=128)
// C[M,NC] = A[M,128] @ B, B row-major [128,NC] (TB=false) or stored [NC,128]
// with logical B[k][n] = Bstore[n][k] (TB=true). Optional bias + leaky act.

template <bool TB, int ACT>
__global__ void __launch_bounds__(256) k_gemm(
    const float* __restrict__ A, const float* __restrict__ B,
    const float* __restrict__ bias, float* __restrict__ C, int NC)
{
    __shared__ float As[32][68];   // [k][m], padded
    __shared__ float Bs[32][132];  // [k][n], padded
    int m0 = blockIdx.x * 64;
    int n0 = blockIdx.y * 128;
    int tid = threadIdx.x;
    int tx = tid & 31;   // col group: cols tx*4 .. tx*4+3
    int ty = tid >> 5;   // row group: rows ty*8 .. ty*8+7

    float acc[8][4];
#pragma unroll
    for (int i = 0; i < 8; i++)
#pragma unroll
        for (int j = 0; j < 4; j++) acc[i][j] = 0.f;

    for (int kc = 0; kc < 128; kc += 32) {
        { // A chunk: 64 rows x 32 k
            int k = tid & 31, r0 = tid >> 5;
#pragma unroll
            for (int i = 0; i < 8; i++) {
                int rr = r0 + i * 8;
                int gm = m0 + rr;
                As[k][rr] = (gm < N_NODES) ? A[(long)gm * 128 + kc + k] : 0.f;
            }
        }
        if (!TB) { // B row-major [128, NC]
            int n = tid & 127, kb = tid >> 7;
#pragma unroll
            for (int j = 0; j < 16; j++) {
                int k = kb + j * 2;
                Bs[k][n] = B[(long)(kc + k) * NC + n0 + n];
            }
        } else {   // B stored [NC, 128]; logical B[k][n] = Bst[n][k]
            int k = tid & 31, nb = tid >> 5;
#pragma unroll
            for (int j = 0; j < 16; j++) {
                int nn = nb + j * 8;
                Bs[k][nn] = B[(long)(n0 + nn) * 128 + kc + k];
            }
        }
        __syncthreads();
#pragma unroll
        for (int k = 0; k < 32; k++) {
            float4 b4 = *(const float4*)&Bs[k][tx * 4];
            float4 a0 = *(const float4*)&As[k][ty * 8];
            float4 a1 = *(const float4*)&As[k][ty * 8 + 4];
            float av[8] = {a0.x, a0.y, a0.z, a0.w, a1.x, a1.y, a1.z, a1.w};
            float bv[4] = {b4.x, b4.y, b4.z, b4.w};
#pragma unroll
            for (int i = 0; i < 8; i++)
#pragma unroll
                for (int j = 0; j < 4; j++)
                    acc[i][j] = fmaf(av[i], bv[j], acc[i][j]);
        }
        __syncthreads();
    }

    float bv[4] = {0.f, 0.f, 0.f, 0.f};
    if (bias) {
#pragma unroll
        for (int j = 0; j < 4; j++) bv[j] = bias[n0 + tx * 4 + j];
    }
#pragma unroll
    for (int i = 0; i < 8; i++) {
        int gm = m0 + ty * 8 + i;
        if (gm < N_NODES) {
            float4 o;
            o.x = acc[i][0] + bv[0];
            o.y = acc[i][1] + bv[1];
            o.z = acc[i][2] + bv[2];
            o.w = acc[i][3] + bv[3];
            if (ACT == 1) { o.x = leaky(o.x); o.y = leaky(o.y); o.z = leaky(o.z); o.w = leaky(o.w); }
            *(float4*)&C[(long)gm * NC + n0 + tx * 4] = o;
        }
    }
}

// ---------------------------------------------------------------- aggregation
// warp-per-node pull from CSR; features as float4 (lane f4 = 4 feats)

__global__ void k_gcn_agg(const float* __restrict__ xw, const float* __restrict__ bias,
                          float* __restrict__ hout, float* __restrict__ gout)
{
    int v = blockIdx.x * 8 + (threadIdx.x >> 5);
    if (v >= N_NODES) return;
    int lane = threadIdx.x & 31;
    const float4* x4 = (const float4*)xw;
    float4 acc = make_float4(0.f, 0.f, 0.f, 0.f);
    float dv = d_dinv[v];
    int s = d_off[v], e = d_off[v + 1];
    for (int i = s; i < e; i++) {
        int u = d_csr[i];
        float c = d_dinv[u] * dv;
        float4 t = x4[(long)u * 32 + lane];
        acc.x += t.x * c; acc.y += t.y * c; acc.z += t.z * c; acc.w += t.w * c;
    }
    float4 slf = x4[(long)v * 32 + lane];
    float sc = dv * dv;
    float4 b = ((const float4*)bias)[lane];
    acc.x = leaky(acc.x + slf.x * sc + b.x);
    acc.y = leaky(acc.y + slf.y * sc + b.y);
    acc.z = leaky(acc.z + slf.z * sc + b.z);
    acc.w = leaky(acc.w + slf.w * sc + b.w);
    ((float4*)hout)[(long)v * 32 + lane] = acc;
    ((float4*)gout)[(long)v * 32 + lane] = acc;
}

__global__ void k_gg_agg(const float* __restrict__ gw, float* __restrict__ mout) {
    int v = blockIdx.x * 8 + (threadIdx.x >> 5);
    if (v >= N_NODES) return;
    int lane = threadIdx.x & 31;
    const float4* x4 = (const float4*)gw;
    float4 acc = make_float4(0.f, 0.f, 0.f, 0.f);
    int s = d_off[v], e = d_off[v + 1];
    for (int i = s; i < e; i++) {
        int u = d_csr[i];
        float4 t = x4[(long)u * 32 + lane];
        acc.x += t.x; acc.y += t.y; acc.z += t.z; acc.w += t.w;
    }
    ((float4*)mout)[(long)v * 32 + lane] = acc;
}

// ---------------------------------------------------------------- elementwise

__global__ void k_gru(const float* __restrict__ gi, const float* __restrict__ gh,
                      float* __restrict__ g)
{
    long i = (long)blockIdx.x * blockDim.x + threadIdx.x;
    if (i >= NHF) return;
    int v = (int)(i >> 7);
    int f = (int)(i & 127);
    long b3 = (long)v * 384;
    float ir = gi[b3 + f], iz = gi[b3 + 128 + f], in_ = gi[b3 + 256 + f];
    float hr = gh[b3 + f], hz = gh[b3 + 128 + f], hn = gh[b3 + 256 + f];
    float r = sigm(ir + hr);
    float z = sigm(iz + hz);
    float n = tanhf(in_ + r * hn);
    float hv = g[i];
    g[i] = (1.f - z) * n + z * hv;
}

__global__ void k_resid(const float* __restrict__ g, float* __restrict__ h) {
    long i = (long)blockIdx.x * blockDim.x + threadIdx.x;
    if (i < NHF) h[i] = leaky(g[i]) + h[i];
}

__global__ void k_probs(const float* __restrict__ t, const float* __restrict__ W2,
                        const float* __restrict__ b2)
{
    int v = blockIdx.x * 8 + (threadIdx.x >> 5);
    if (v >= N_NODES) return;
    int lane = threadIdx.x & 31;
    float4 tv = ((const float4*)t)[(long)v * 32 + lane];
    float4 wv = ((const float4*)W2)[lane];
    float s = tv.x * wv.x + tv.y * wv.y + tv.z * wv.z + tv.w * wv.w;
#pragma unroll
    for (int o = 16; o; o >>= 1) s += __shfl_xor_sync(0xffffffffu, s, o);
    if (lane == 0) d_probs[v] = sigm(s + b2[0]);
}

// ---------------------------------------------------------------- loss

__global__ void k_loss_nodes(const int* __restrict__ batch, float* __restrict__ out) {
    __shared__ float sm[NGRAPH];
    if (threadIdx.x < NGRAPH) sm[threadIdx.x] = 0.f;
    __syncthreads();
    for (int v = blockIdx.x * blockDim.x + threadIdx.x; v < N_NODES;
         v += gridDim.x * blockDim.x) {
        float w = -0.5f * d_probs[v] * (float)d_degr[v];
        atomicAdd(&sm[batch[v]], w);
    }
    __syncthreads();
    if (threadIdx.x < NGRAPH) atomicAdd(&out[threadIdx.x], sm[threadIdx.x]);
}

__global__ void k_loss_edges(const int* __restrict__ row, const int* __restrict__ col,
                             const int* __restrict__ batch, float* __restrict__ out)
{
    __shared__ float sm[NGRAPH];
    if (threadIdx.x < NGRAPH) sm[threadIdx.x] = 0.f;
    __syncthreads();
    for (int e = blockIdx.x * blockDim.x + threadIdx.x; e < N_EDGES;
         e += gridDim.x * blockDim.x) {
        int r = row[e];
        float w = 0.5f * d_probs[r] * d_probs[col[e]];
        atomicAdd(&sm[batch[r]], w);
    }
    __syncthreads();
    if (threadIdx.x < NGRAPH) atomicAdd(&out[threadIdx.x], sm[threadIdx.x]);
}

// ---------------------------------------------------------------- launch

extern "C" void kernel_launch(void* const* d_in, const int* in_sizes, int n_in,
                              void* d_out, int out_size)
{
    const float* x     = (const float*)d_in[0];
    const int*   ei    = (const int*)d_in[1];
    const int*   batch = (const int*)d_in[2];
    const float* W_gcn = (const float*)d_in[3];
    const float* b_gcn = (const float*)d_in[4];
    const float* W_gg  = (const float*)d_in[5];
    const float* W_ih  = (const float*)d_in[6];
    const float* W_hh  = (const float*)d_in[7];
    const float* b_ih  = (const float*)d_in[8];
    const float* b_hh  = (const float*)d_in[9];
    const float* W1    = (const float*)d_in[10];
    const float* b1    = (const float*)d_in[11];
    const float* W2    = (const float*)d_in[12];
    const float* b2    = (const float*)d_in[13];
    float* out = (float*)d_out;
    const int* row = ei;
    const int* col = ei + N_EDGES;

    float* S = nullptr;
    cudaGetSymbolAddress((void**)&S, d_scratch);
    float* XW = S;
    float* Hb = S + 1 * NHF;
    float* Gb = S + 2 * NHF;
    float* Mb = S + 3 * NHF;
    float* GI = S + 4 * NHF;
    float* GH = S + 7 * NHF;

    // CSR build (per replay; cheap, deterministic up to fp-sum order)
    k_zero<<<196, 256>>>(out);
    k_count<<<3125, 256>>>(row, col);
    k_dinv<<<196, 256>>>();
    k_scan<<<1, 1024>>>();
    k_scatter<<<3125, 256>>>(row, col);

    dim3 g1(782, 1), g3(782, 3);

    // GCN
    k_gemm<false, 0><<<g1, 256>>>(x, W_gcn, nullptr, XW, 128);
    k_gcn_agg<<<6250, 256>>>(XW, b_gcn, Hb, Gb);

    // 3x GatedGraphConv + GRU
    for (int l = 0; l < 3; l++) {
        k_gemm<false, 0><<<g1, 256>>>(Gb, W_gg + (long)l * 128 * 128, nullptr, XW, 128);
        k_gg_agg<<<6250, 256>>>(XW, Mb);
        k_gemm<true, 0><<<g3, 256>>>(Mb, W_ih, b_ih, GI, 384);
        k_gemm<true, 0><<<g3, 256>>>(Gb, W_hh, b_hh, GH, 384);
        k_gru<<<25000, 256>>>(GI, GH, Gb);
    }

    // head
    k_resid<<<25000, 256>>>(Gb, Hb);
    k_gemm<false, 1><<<g1, 256>>>(Hb, W1, b1, XW, 128);
    k_probs<<<6250, 256>>>(XW, W2, b2);

    // loss
    k_loss_nodes<<<512, 256>>>(batch, out);
    k_loss_edges<<<512, 256>>>(row, col, batch, out);
}

// round 6
// speedup vs baseline: 1.6745x; 1.6725x over previous
#include <cuda_runtime.h>
#include <cuda_bf16.h>
#include <math.h>
#include <stdint.h>

#define N_NODES 50000
#define N_EDGES 800000
#define NGRAPH  64
#define NEG     0.01f
#define MTILES  391   // ceil(50000/128)
#define KEXT    384
#define LDSW    72    // padded smem row stride (bf16 elems) = 144B

// ---------------- device globals ----------------
__device__ float d_XW[6400000];
__device__ float d_Hb[6400000];
__device__ float d_Gb[6400000];
__device__ float d_GI[19200000];
__device__ float d_GH[19200000];
__device__ __nv_bfloat16 d_xext[19200000];   // A-ext [hi|lo|hi], K=384
__device__ __nv_bfloat16 d_gext[19200000];
__device__ __nv_bfloat16 d_mext[19200000];
__device__ __nv_bfloat16 d_hext[19200000];
__device__ __nv_bfloat16 d_wext[540672];     // 1408 rows x 384, B-ext [hi|hi|lo]
__device__ float d_dinv[N_NODES];
__device__ float d_probs[N_NODES];
__device__ int d_degc[N_NODES];
__device__ int d_degr[N_NODES];
__device__ int d_fill[N_NODES];
__device__ int d_off[N_NODES + 1];
__device__ int d_csr[N_EDGES];
__device__ int d_bsum[256];

__device__ __forceinline__ float leaky(float x) { return x > 0.f ? x : NEG * x; }
__device__ __forceinline__ float sigm(float x)  { return 1.f / (1.f + __expf(-x)); }

__device__ __forceinline__ uint32_t smem_u32(const void* p) {
    uint32_t a;
    asm("{ .reg .u64 t; cvta.to.shared.u64 t, %1; cvt.u32.u64 %0, t; }" : "=r"(a) : "l"(p));
    return a;
}
__device__ __forceinline__ void cp16(uint32_t dst, const void* src, bool valid) {
    int sz = valid ? 16 : 0;
    asm volatile("cp.async.cg.shared.global [%0], [%1], 16, %2;"
                 :: "r"(dst), "l"(src), "r"(sz));
}
__device__ __forceinline__ void cp_commit() {
    asm volatile("cp.async.commit_group;");
}
__device__ __forceinline__ void ldmx4(uint32_t* r, uint32_t addr) {
    asm volatile("ldmatrix.sync.aligned.m8n8.x4.shared.b16 {%0,%1,%2,%3}, [%4];"
                 : "=r"(r[0]), "=r"(r[1]), "=r"(r[2]), "=r"(r[3]) : "r"(addr));
}
__device__ __forceinline__ void mma16816(float* c, const uint32_t* a, const uint32_t* b) {
    asm volatile(
        "mma.sync.aligned.m16n8k16.row.col.f32.bf16.bf16.f32 "
        "{%0,%1,%2,%3}, {%4,%5,%6,%7}, {%8,%9}, {%0,%1,%2,%3};"
        : "+f"(c[0]), "+f"(c[1]), "+f"(c[2]), "+f"(c[3])
        : "r"(a[0]), "r"(a[1]), "r"(a[2]), "r"(a[3]), "r"(b[0]), "r"(b[1]));
}

// split fp32x4 -> A-ext [hi|lo|hi] at p, p+128, p+256
__device__ __forceinline__ void st_splitA(__nv_bfloat16* p, float4 v) {
    __nv_bfloat162 h0 = __floats2bfloat162_rn(v.x, v.y);
    __nv_bfloat162 h1 = __floats2bfloat162_rn(v.z, v.w);
    __nv_bfloat162 l0 = __floats2bfloat162_rn(v.x - __bfloat162float(h0.x),
                                              v.y - __bfloat162float(h0.y));
    __nv_bfloat162 l1 = __floats2bfloat162_rn(v.z - __bfloat162float(h1.x),
                                              v.w - __bfloat162float(h1.y));
    ((__nv_bfloat162*)p)[0] = h0;         ((__nv_bfloat162*)p)[1] = h1;
    ((__nv_bfloat162*)(p + 128))[0] = l0; ((__nv_bfloat162*)(p + 128))[1] = l1;
    ((__nv_bfloat162*)(p + 256))[0] = h0; ((__nv_bfloat162*)(p + 256))[1] = h1;
}

// ---------------- CSR build ----------------
__global__ void k_zero(float* out) {
    int i = blockIdx.x * blockDim.x + threadIdx.x;
    if (i < N_NODES) { d_degc[i] = 0; d_degr[i] = 0; d_fill[i] = 0; }
    if (i < NGRAPH) out[i] = 0.f;
}
__global__ void k_count(const int* __restrict__ row, const int* __restrict__ col) {
    int e = blockIdx.x * blockDim.x + threadIdx.x;
    if (e < N_EDGES) { atomicAdd(&d_degc[col[e]], 1); atomicAdd(&d_degr[row[e]], 1); }
}
__global__ void k_dinv() {
    int i = blockIdx.x * blockDim.x + threadIdx.x;
    if (i < N_NODES) d_dinv[i] = rsqrtf((float)d_degc[i] + 1.f);
}
__global__ void k_scan1() {
    __shared__ int sm[256];
    int i = blockIdx.x * 256 + threadIdx.x;
    sm[threadIdx.x] = (i < N_NODES) ? d_degc[i] : 0;
    __syncthreads();
    for (int o = 128; o; o >>= 1) {
        if (threadIdx.x < o) sm[threadIdx.x] += sm[threadIdx.x + o];
        __syncthreads();
    }
    if (threadIdx.x == 0) d_bsum[blockIdx.x] = sm[0];
}
__global__ void k_scan2() {
    __shared__ int sm[256];
    int t = threadIdx.x;
    int v = (t < 196) ? d_bsum[t] : 0;
    sm[t] = v; __syncthreads();
    for (int o = 1; o < 256; o <<= 1) {
        int x = (t >= o) ? sm[t - o] : 0;
        __syncthreads(); sm[t] += x; __syncthreads();
    }
    if (t < 196) d_bsum[t] = sm[t] - v;
    if (t == 0) d_off[N_NODES] = N_EDGES;
}
__global__ void k_scan3() {
    __shared__ int sm[256];
    int t = threadIdx.x, i = blockIdx.x * 256 + t;
    int v = (i < N_NODES) ? d_degc[i] : 0;
    sm[t] = v; __syncthreads();
    for (int o = 1; o < 256; o <<= 1) {
        int x = (t >= o) ? sm[t - o] : 0;
        __syncthreads(); sm[t] += x; __syncthreads();
    }
    if (i < N_NODES) d_off[i] = d_bsum[blockIdx.x] + sm[t] - v;
}
__global__ void k_scatter(const int* __restrict__ row, const int* __restrict__ col) {
    int e = blockIdx.x * blockDim.x + threadIdx.x;
    if (e < N_EDGES) {
        int c = col[e];
        d_csr[d_off[c] + atomicAdd(&d_fill[c], 1)] = row[e];
    }
}

// ---------------- splits ----------------
__global__ void k_split_x(const float* __restrict__ x) {
    long idx = (long)blockIdx.x * 256 + threadIdx.x;
    if (idx >= 1600000L) return;
    long v = idx >> 5; int q = (int)(idx & 31);
    st_splitA(d_xext + v * KEXT + q * 4, ((const float4*)x)[idx]);
}
__global__ void k_split_w(const float* __restrict__ Wgcn, const float* __restrict__ Wgg,
                          const float* __restrict__ Wih, const float* __restrict__ Whh,
                          const float* __restrict__ W1) {
    int idx = blockIdx.x * 256 + threadIdx.x;
    if (idx >= 1408 * 128) return;
    int r = idx >> 7, k = idx & 127;
    float v;
    if (r < 128)        v = Wgcn[k * 128 + r];
    else if (r < 512)  { int l = (r - 128) >> 7, n = (r - 128) & 127; v = Wgg[l * 16384 + k * 128 + n]; }
    else if (r < 896)  { int n = r - 512;  v = Wih[n * 128 + k]; }
    else if (r < 1280) { int n = r - 896;  v = Whh[n * 128 + k]; }
    else               { int n = r - 1280; v = W1[k * 128 + n]; }
    __nv_bfloat16 h  = __float2bfloat16(v);
    __nv_bfloat16 lo = __float2bfloat16(v - __bfloat162float(h));
    __nv_bfloat16* dst = d_wext + (long)r * KEXT;
    dst[k] = h; dst[128 + k] = h; dst[256 + k] = lo;   // B-ext [hi|hi|lo]
}

// ---------------- HMMA split-bf16 GEMM ----------------
// C[m][n0+n] = sum_{k=0..383} A[m][k] * B[n0_rows + n][k]
// grid (MTILES, n_tiles). EPI 0 = plain store, 1 = bias+leaky.
template <int EPI>
__global__ void __launch_bounds__(256) k_mm(
    const __nv_bfloat16* __restrict__ A, const __nv_bfloat16* __restrict__ B,
    const float* __restrict__ bias, float* __restrict__ C, int NC)
{
    extern __shared__ __align__(16) char smraw[];
    uint32_t smb = smem_u32(smraw);
    const int tid = threadIdx.x, lane = tid & 31, wid = tid >> 5;
    const int mw = (wid >> 1) * 32;      // warp M offset (0,32,64,96)
    const int nw = (wid & 1) * 64;       // warp N offset (0,64)
    const long m0 = (long)blockIdx.x * 128;
    const int nb = blockIdx.y * 128;     // B row offset / C col offset

    float acc[2][8][4];
#pragma unroll
    for (int i = 0; i < 2; i++)
#pragma unroll
        for (int j = 0; j < 8; j++)
#pragma unroll
            for (int e = 0; e < 4; e++) acc[i][j][e] = 0.f;

    // loader lambda-ish: stage s covers k chunk kc
    const int lrow = tid >> 3;            // one of 32 rows per pass? no: c>>3
    (void)lrow;
#define LOAD_STAGE(st, kc)                                                        \
    {                                                                             \
        uint32_t aA = smb + (st) * 36864;                                         \
        uint32_t aB = aA + 18432;                                                 \
        _Pragma("unroll")                                                         \
        for (int i_ = 0; i_ < 4; i_++) {                                          \
            int c_ = tid + i_ * 256;                                              \
            int row_ = c_ >> 3, col8_ = (c_ & 7) * 8;                             \
            long gr_ = m0 + row_;                                                 \
            bool v_ = gr_ < N_NODES;                                              \
            const __nv_bfloat16* sA_ = A + (v_ ? gr_ * KEXT + (kc) + col8_ : 0);  \
            cp16(aA + (row_ * LDSW + col8_) * 2, sA_, v_);                        \
            const __nv_bfloat16* sB_ = B + (long)(nb + row_) * KEXT + (kc) + col8_; \
            cp16(aB + (row_ * LDSW + col8_) * 2, sB_, true);                      \
        }                                                                         \
        cp_commit();                                                              \
    }

    LOAD_STAGE(0, 0);

    const int arow = mw + (lane & 15);
    const int brow = nw + (lane & 15);
    const int acol = (lane >> 4) * 8;

#pragma unroll 1
    for (int ch = 0; ch < 6; ch++) {
        if (ch < 5) LOAD_STAGE((ch + 1) & 1, (ch + 1) * 64);
        if (ch < 5) asm volatile("cp.async.wait_group 1;");
        else        asm volatile("cp.async.wait_group 0;");
        __syncthreads();
        uint32_t sA = smb + (ch & 1) * 36864;
        uint32_t sB = sA + 18432;
#pragma unroll
        for (int ks = 0; ks < 4; ks++) {
            int k0 = ks * 16;
            uint32_t af[2][4], bf[8][2];
#pragma unroll
            for (int i = 0; i < 2; i++)
                ldmx4(af[i], sA + ((arow + i * 16) * LDSW + k0 + acol) * 2);
#pragma unroll
            for (int j2 = 0; j2 < 4; j2++) {
                uint32_t t[4];
                ldmx4(t, sB + ((brow + j2 * 16) * LDSW + k0 + acol) * 2);
                bf[2 * j2][0] = t[0]; bf[2 * j2 + 1][0] = t[1];
                bf[2 * j2][1] = t[2]; bf[2 * j2 + 1][1] = t[3];
            }
#pragma unroll
            for (int i = 0; i < 2; i++)
#pragma unroll
                for (int j = 0; j < 8; j++)
                    mma16816(acc[i][j], af[i], bf[j]);
        }
        __syncthreads();
    }

    // epilogue
    const int r_in = lane >> 2;           // 0..7
    const int cpair = (lane & 3) * 2;     // 0,2,4,6
#pragma unroll
    for (int i = 0; i < 2; i++) {
        long gm = m0 + mw + i * 16 + r_in;
#pragma unroll
        for (int j = 0; j < 8; j++) {
            int colg = nb + nw + j * 8 + cpair;
            float2 v0 = make_float2(acc[i][j][0], acc[i][j][1]);
            float2 v1 = make_float2(acc[i][j][2], acc[i][j][3]);
            if (EPI == 1) {
                float bx = bias[colg], by = bias[colg + 1];
                v0.x = leaky(v0.x + bx); v0.y = leaky(v0.y + by);
                v1.x = leaky(v1.x + bx); v1.y = leaky(v1.y + by);
            }
            if (gm < N_NODES)     *(float2*)&C[gm * NC + colg] = v0;
            if (gm + 8 < N_NODES) *(float2*)&C[(gm + 8) * NC + colg] = v1;
        }
    }
#undef LOAD_STAGE
}

// ---------------- aggregation (pull-CSR, warp per node) ----------------
__global__ void k_gcn_agg(const float* __restrict__ bias) {
    int v = blockIdx.x * 8 + (threadIdx.x >> 5);
    if (v >= N_NODES) return;
    int lane = threadIdx.x & 31;
    const float4* x4 = (const float4*)d_XW;
    float4 acc = make_float4(0.f, 0.f, 0.f, 0.f);
    float dv = d_dinv[v];
    int s = d_off[v], e = d_off[v + 1];
    for (int i = s; i < e; i++) {
        int u = d_csr[i];
        float c = d_dinv[u] * dv;
        float4 t = x4[(long)u * 32 + lane];
        acc.x += t.x * c; acc.y += t.y * c; acc.z += t.z * c; acc.w += t.w * c;
    }
    float4 slf = x4[(long)v * 32 + lane];
    float sc = dv * dv;
    float4 b = ((const float4*)bias)[lane];
    acc.x = leaky(acc.x + slf.x * sc + b.x);
    acc.y = leaky(acc.y + slf.y * sc + b.y);
    acc.z = leaky(acc.z + slf.z * sc + b.z);
    acc.w = leaky(acc.w + slf.w * sc + b.w);
    ((float4*)d_Hb)[(long)v * 32 + lane] = acc;
    ((float4*)d_Gb)[(long)v * 32 + lane] = acc;
    st_splitA(d_gext + (long)v * KEXT + lane * 4, acc);
}

__global__ void k_gg_agg() {
    int v = blockIdx.x * 8 + (threadIdx.x >> 5);
    if (v >= N_NODES) return;
    int lane = threadIdx.x & 31;
    const float4* x4 = (const float4*)d_XW;
    float4 acc = make_float4(0.f, 0.f, 0.f, 0.f);
    int s = d_off[v], e = d_off[v + 1];
    for (int i = s; i < e; i++) {
        int u = d_csr[i];
        float4 t = x4[(long)u * 32 + lane];
        acc.x += t.x; acc.y += t.y; acc.z += t.z; acc.w += t.w;
    }
    st_splitA(d_mext + (long)v * KEXT + lane * 4, acc);
}

// ---------------- GRU elementwise (+ split producer) ----------------
__global__ void k_gru(const float* __restrict__ b_ih, const float* __restrict__ b_hh) {
    long idx = (long)blockIdx.x * 256 + threadIdx.x;
    if (idx >= 1600000L) return;          // 50000 * 32 quads
    long v = idx >> 5; int f = (int)(idx & 31) * 4;
    long bi = v * 384, bg = v * 128;
    float4 ir = *(const float4*)&d_GI[bi + f];
    float4 iz = *(const float4*)&d_GI[bi + 128 + f];
    float4 in = *(const float4*)&d_GI[bi + 256 + f];
    float4 hr = *(const float4*)&d_GH[bi + f];
    float4 hz = *(const float4*)&d_GH[bi + 128 + f];
    float4 hn = *(const float4*)&d_GH[bi + 256 + f];
    float4 bir = *(const float4*)&b_ih[f];
    float4 biz = *(const float4*)&b_ih[128 + f];
    float4 bin = *(const float4*)&b_ih[256 + f];
    float4 bhr = *(const float4*)&b_hh[f];
    float4 bhz = *(const float4*)&b_hh[128 + f];
    float4 bhn = *(const float4*)&b_hh[256 + f];
    float4 go = *(const float4*)&d_Gb[bg + f];
    float g[4];
#pragma unroll
    for (int e = 0; e < 4; e++) {
        float r = sigm((&ir.x)[e] + (&bir.x)[e] + (&hr.x)[e] + (&bhr.x)[e]);
        float z = sigm((&iz.x)[e] + (&biz.x)[e] + (&hz.x)[e] + (&bhz.x)[e]);
        float n = tanhf((&in.x)[e] + (&bin.x)[e] + r * ((&hn.x)[e] + (&bhn.x)[e]));
        g[e] = (1.f - z) * n + z * (&go.x)[e];
    }
    float4 gv = make_float4(g[0], g[1], g[2], g[3]);
    *(float4*)&d_Gb[bg + f] = gv;
    st_splitA(d_gext + bi + f, gv);
}

// ---------------- head / elementwise ----------------
__global__ void k_resid() {
    long idx = (long)blockIdx.x * 256 + threadIdx.x;
    if (idx >= 1600000L) return;
    float4 g = ((const float4*)d_Gb)[idx];
    float4 hh = ((const float4*)d_Hb)[idx];
    float4 t;
    t.x = leaky(g.x) + hh.x; t.y = leaky(g.y) + hh.y;
    t.z = leaky(g.z) + hh.z; t.w = leaky(g.w) + hh.w;
    long v = idx >> 5; int q = (int)(idx & 31);
    st_splitA(d_hext + v * KEXT + q * 4, t);
}

__global__ void k_probs(const float* __restrict__ W2, const float* __restrict__ b2) {
    int v = blockIdx.x * 8 + (threadIdx.x >> 5);
    if (v >= N_NODES) return;
    int lane = threadIdx.x & 31;
    float4 tv = ((const float4*)d_XW)[(long)v * 32 + lane];
    float4 wv = ((const float4*)W2)[lane];
    float s = tv.x * wv.x + tv.y * wv.y + tv.z * wv.z + tv.w * wv.w;
#pragma unroll
    for (int o = 16; o; o >>= 1) s += __shfl_xor_sync(0xffffffffu, s, o);
    if (lane == 0) d_probs[v] = sigm(s + b2[0]);
}

// ---------------- loss ----------------
__global__ void k_loss_nodes(const int* __restrict__ batch, float* __restrict__ out) {
    __shared__ float sm[NGRAPH];
    if (threadIdx.x < NGRAPH) sm[threadIdx.x] = 0.f;
    __syncthreads();
    for (int v = blockIdx.x * blockDim.x + threadIdx.x; v < N_NODES;
         v += gridDim.x * blockDim.x)
        atomicAdd(&sm[batch[v]], -0.5f * d_probs[v] * (float)d_degr[v]);
    __syncthreads();
    if (threadIdx.x < NGRAPH) atomicAdd(&out[threadIdx.x], sm[threadIdx.x]);
}
__global__ void k_loss_edges(const int* __restrict__ row, const int* __restrict__ col,
                             const int* __restrict__ batch, float* __restrict__ out) {
    __shared__ float sm[NGRAPH];
    if (threadIdx.x < NGRAPH) sm[threadIdx.x] = 0.f;
    __syncthreads();
    for (int e = blockIdx.x * blockDim.x + threadIdx.x; e < N_EDGES;
         e += gridDim.x * blockDim.x) {
        int r = row[e];
        atomicAdd(&sm[batch[r]], 0.5f * d_probs[r] * d_probs[col[e]]);
    }
    __syncthreads();
    if (threadIdx.x < NGRAPH) atomicAdd(&out[threadIdx.x], sm[threadIdx.x]);
}

// ---------------- launch ----------------
extern "C" void kernel_launch(void* const* d_in, const int* in_sizes, int n_in,
                              void* d_out, int out_size)
{
    const float* x     = (const float*)d_in[0];
    const int*   ei    = (const int*)d_in[1];
    const int*   batch = (const int*)d_in[2];
    const float* W_gcn = (const float*)d_in[3];
    const float* b_gcn = (const float*)d_in[4];
    const float* W_gg  = (const float*)d_in[5];
    const float* W_ih  = (const float*)d_in[6];
    const float* W_hh  = (const float*)d_in[7];
    const float* b_ih  = (const float*)d_in[8];
    const float* b_hh  = (const float*)d_in[9];
    const float* W1    = (const float*)d_in[10];
    const float* b1    = (const float*)d_in[11];
    const float* W2    = (const float*)d_in[12];
    const float* b2    = (const float*)d_in[13];
    float* out = (float*)d_out;
    const int* row = ei;
    const int* col = ei + N_EDGES;

    const int SMEM = 2 * 36864;   // 73,728 B (2-stage double buffer)
    cudaFuncSetAttribute(k_mm<0>, cudaFuncAttributeMaxDynamicSharedMemorySize, SMEM);
    cudaFuncSetAttribute(k_mm<1>, cudaFuncAttributeMaxDynamicSharedMemorySize, SMEM);

    __nv_bfloat16 *xext, *gext, *mext, *hext, *wext;
    float *XW, *GI, *GH;
    cudaGetSymbolAddress((void**)&xext, d_xext);
    cudaGetSymbolAddress((void**)&gext, d_gext);
    cudaGetSymbolAddress((void**)&mext, d_mext);
    cudaGetSymbolAddress((void**)&hext, d_hext);
    cudaGetSymbolAddress((void**)&wext, d_wext);
    cudaGetSymbolAddress((void**)&XW, d_XW);
    cudaGetSymbolAddress((void**)&GI, d_GI);
    cudaGetSymbolAddress((void**)&GH, d_GH);

    // CSR build + operand splits
    k_zero<<<196, 256>>>(out);
    k_count<<<3125, 256>>>(row, col);
    k_dinv<<<196, 256>>>();
    k_scan1<<<196, 256>>>();
    k_scan2<<<1, 256>>>();
    k_scan3<<<196, 256>>>();
    k_scatter<<<3125, 256>>>(row, col);
    k_split_x<<<6250, 256>>>(x);
    k_split_w<<<704, 256>>>(W_gcn, W_gg, W_ih, W_hh, W1);

    dim3 g1(MTILES, 1), g3(MTILES, 3);

    // GCN
    k_mm<0><<<g1, 256, SMEM>>>(xext, wext, nullptr, XW, 128);
    k_gcn_agg<<<6250, 256>>>(b_gcn);

    // 3x GatedGraphConv + GRU
    for (int l = 0; l < 3; l++) {
        k_mm<0><<<g1, 256, SMEM>>>(gext, wext + (long)(128 + 128 * l) * KEXT,
                                   nullptr, XW, 128);
        k_gg_agg<<<6250, 256>>>();
        k_mm<0><<<g3, 256, SMEM>>>(mext, wext + 512L * KEXT, nullptr, GI, 384);
        k_mm<0><<<g3, 256, SMEM>>>(gext, wext + 896L * KEXT, nullptr, GH, 384);
        k_gru<<<6250, 256>>>(b_ih, b_hh);
    }

    // head
    k_resid<<<6250, 256>>>();
    k_mm<1><<<g1, 256, SMEM>>>(hext, wext + 1280L * KEXT, b1, XW, 128);
    k_probs<<<6250, 256>>>(W2, b2);

    // loss
    k_loss_nodes<<<512, 256>>>(batch, out);
    k_loss_edges<<<512, 256>>>(row, col, batch, out);
}

// round 8
// speedup vs baseline: 1.9497x; 1.1644x over previous
#include <cuda_runtime.h>
#include <cuda_fp16.h>
#include <math.h>
#include <stdint.h>

#define N_NODES 50000
#define N_EDGES 800000
#define NGRAPH  64
#define NEG     0.01f
#define MTILES  391   // ceil(50000/128)
#define LDSW    72    // padded smem row stride (half elems) = 144B

// ---------------- device globals ----------------
__device__ float d_XW[6400000];
__device__ float d_Hb[6400000];
__device__ float d_Gb[6400000];
__device__ __half d_xext[12800000];   // [N,256] A-ext [hi|lo]
__device__ __half d_gext[12800000];
__device__ __half d_mext[12800000];
__device__ __half d_hext[12800000];
__device__ __half d_wext[360448];     // 1408 rows x 256, B-ext [hi|hi]
__device__ float d_dinv[N_NODES];
__device__ float d_probs[N_NODES];
__device__ int d_degc[N_NODES];
__device__ int d_degr[N_NODES];
__device__ int d_fill[N_NODES];
__device__ int d_off[N_NODES + 1];
__device__ int d_csr[N_EDGES];
__device__ int d_bsum[256];

__device__ __forceinline__ float leaky(float x) { return x > 0.f ? x : NEG * x; }
__device__ __forceinline__ float sigm(float x)  { return 1.f / (1.f + __expf(-x)); }

__device__ __forceinline__ uint32_t smem_u32(const void* p) {
    uint32_t a;
    asm("{ .reg .u64 t; cvta.to.shared.u64 t, %1; cvt.u32.u64 %0, t; }" : "=r"(a) : "l"(p));
    return a;
}
__device__ __forceinline__ void cp16(uint32_t dst, const void* src, bool valid) {
    int sz = valid ? 16 : 0;
    asm volatile("cp.async.cg.shared.global [%0], [%1], 16, %2;"
                 :: "r"(dst), "l"(src), "r"(sz));
}
__device__ __forceinline__ void cp_commit() { asm volatile("cp.async.commit_group;"); }
__device__ __forceinline__ void ldmx4(uint32_t* r, uint32_t addr) {
    asm volatile("ldmatrix.sync.aligned.m8n8.x4.shared.b16 {%0,%1,%2,%3}, [%4];"
                 : "=r"(r[0]), "=r"(r[1]), "=r"(r[2]), "=r"(r[3]) : "r"(addr));
}
__device__ __forceinline__ void mma16816(float* c, const uint32_t* a, uint32_t b0, uint32_t b1) {
    asm volatile(
        "mma.sync.aligned.m16n8k16.row.col.f32.f16.f16.f32 "
        "{%0,%1,%2,%3}, {%4,%5,%6,%7}, {%8,%9}, {%0,%1,%2,%3};"
        : "+f"(c[0]), "+f"(c[1]), "+f"(c[2]), "+f"(c[3])
        : "r"(a[0]), "r"(a[1]), "r"(a[2]), "r"(a[3]), "r"(b0), "r"(b1));
}

// split fp32x4 -> [hi|lo] at p, p+128
__device__ __forceinline__ void st_splitA(__half* p, float4 v) {
    __half2 h0 = __floats2half2_rn(v.x, v.y);
    __half2 h1 = __floats2half2_rn(v.z, v.w);
    __half2 l0 = __floats2half2_rn(v.x - __half2float(h0.x), v.y - __half2float(h0.y));
    __half2 l1 = __floats2half2_rn(v.z - __half2float(h1.x), v.w - __half2float(h1.y));
    ((__half2*)p)[0] = h0;         ((__half2*)p)[1] = h1;
    ((__half2*)(p + 128))[0] = l0; ((__half2*)(p + 128))[1] = l1;
}
// split fp32x2 -> hi at p, lo at p+128
__device__ __forceinline__ void st_splitA2(__half* p, float a, float b) {
    __half2 h = __floats2half2_rn(a, b);
    __half2 l = __floats2half2_rn(a - __half2float(h.x), b - __half2float(h.y));
    *(__half2*)p = h;
    *(__half2*)(p + 128) = l;
}

// ---------------- CSR build ----------------
__global__ void k_zero(float* out) {
    int i = blockIdx.x * blockDim.x + threadIdx.x;
    if (i < N_NODES) { d_degc[i] = 0; d_degr[i] = 0; d_fill[i] = 0; }
    if (i < NGRAPH) out[i] = 0.f;
}
__global__ void k_count(const int* __restrict__ row, const int* __restrict__ col) {
    int e = blockIdx.x * blockDim.x + threadIdx.x;
    if (e < N_EDGES) { atomicAdd(&d_degc[col[e]], 1); atomicAdd(&d_degr[row[e]], 1); }
}
__global__ void k_dinv() {
    int i = blockIdx.x * blockDim.x + threadIdx.x;
    if (i < N_NODES) d_dinv[i] = rsqrtf((float)d_degc[i] + 1.f);
}
__global__ void k_scan1() {
    __shared__ int sm[256];
    int i = blockIdx.x * 256 + threadIdx.x;
    sm[threadIdx.x] = (i < N_NODES) ? d_degc[i] : 0;
    __syncthreads();
    for (int o = 128; o; o >>= 1) {
        if (threadIdx.x < o) sm[threadIdx.x] += sm[threadIdx.x + o];
        __syncthreads();
    }
    if (threadIdx.x == 0) d_bsum[blockIdx.x] = sm[0];
}
__global__ void k_scan2() {
    __shared__ int sm[256];
    int t = threadIdx.x;
    int v = (t < 196) ? d_bsum[t] : 0;
    sm[t] = v; __syncthreads();
    for (int o = 1; o < 256; o <<= 1) {
        int x = (t >= o) ? sm[t - o] : 0;
        __syncthreads(); sm[t] += x; __syncthreads();
    }
    if (t < 196) d_bsum[t] = sm[t] - v;
    if (t == 0) d_off[N_NODES] = N_EDGES;
}
__global__ void k_scan3() {
    __shared__ int sm[256];
    int t = threadIdx.x, i = blockIdx.x * 256 + t;
    int v = (i < N_NODES) ? d_degc[i] : 0;
    sm[t] = v; __syncthreads();
    for (int o = 1; o < 256; o <<= 1) {
        int x = (t >= o) ? sm[t - o] : 0;
        __syncthreads(); sm[t] += x; __syncthreads();
    }
    if (i < N_NODES) d_off[i] = d_bsum[blockIdx.x] + sm[t] - v;
}
__global__ void k_scatter(const int* __restrict__ row, const int* __restrict__ col) {
    int e = blockIdx.x * blockDim.x + threadIdx.x;
    if (e < N_EDGES) {
        int c = col[e];
        d_csr[d_off[c] + atomicAdd(&d_fill[c], 1)] = row[e];
    }
}

// ---------------- splits ----------------
__global__ void k_split_x(const float* __restrict__ x) {
    long idx = (long)blockIdx.x * 256 + threadIdx.x;
    if (idx >= 1600000L) return;
    long v = idx >> 5; int q = (int)(idx & 31);
    st_splitA(d_xext + v * 256 + q * 4, ((const float4*)x)[idx]);
}
__global__ void k_split_w(const float* __restrict__ Wgcn, const float* __restrict__ Wgg,
                          const float* __restrict__ Wih, const float* __restrict__ Whh,
                          const float* __restrict__ W1) {
    int idx = blockIdx.x * 256 + threadIdx.x;
    if (idx >= 1408 * 128) return;
    int r = idx >> 7, k = idx & 127;
    float v;
    if (r < 128)        v = Wgcn[k * 128 + r];
    else if (r < 512)  { int l = (r - 128) >> 7, n = (r - 128) & 127; v = Wgg[l * 16384 + k * 128 + n]; }
    else if (r < 896)  { int n = r - 512;  v = Wih[n * 128 + k]; }
    else if (r < 1280) { int n = r - 896;  v = Whh[n * 128 + k]; }
    else               { int n = r - 1280; v = W1[k * 128 + n]; }
    __half h = __float2half_rn(v);
    __half* dst = d_wext + (long)r * 256;
    dst[k] = h; dst[128 + k] = h;   // B-ext [hi|hi]
}

// ---------------- HMMA 2-term fp16 GEMM (K=256) ----------------
// C[m][n] = sum_{k<256} A[m][k] * B[n][k]. EPI 0 = plain, 1 = bias+leaky.
template <int EPI>
__global__ void __launch_bounds__(256) k_mm(
    const __half* __restrict__ A, const __half* __restrict__ B,
    const float* __restrict__ bias, float* __restrict__ C)
{
    extern __shared__ __align__(16) char smraw[];
    uint32_t smb = smem_u32(smraw);
    const int tid = threadIdx.x, lane = tid & 31, wid = tid >> 5;
    const int mw = (wid >> 1) * 32;
    const int nw = (wid & 1) * 64;
    const long m0 = (long)blockIdx.x * 128;

    float acc[2][8][4];
#pragma unroll
    for (int i = 0; i < 2; i++)
#pragma unroll
        for (int j = 0; j < 8; j++)
#pragma unroll
            for (int e = 0; e < 4; e++) acc[i][j][e] = 0.f;

#define LOAD_STAGE(st, kc)                                                        \
    {                                                                             \
        uint32_t aA = smb + (st) * 36864;                                         \
        uint32_t aB = aA + 18432;                                                 \
        _Pragma("unroll")                                                         \
        for (int i_ = 0; i_ < 4; i_++) {                                          \
            int c_ = tid + i_ * 256;                                              \
            int row_ = c_ >> 3, col8_ = (c_ & 7) * 8;                             \
            long gr_ = m0 + row_;                                                 \
            bool v_ = gr_ < N_NODES;                                              \
            cp16(aA + (row_ * LDSW + col8_) * 2,                                  \
                 A + (v_ ? gr_ * 256 + (kc) + col8_ : 0), v_);                    \
            cp16(aB + (row_ * LDSW + col8_) * 2,                                  \
                 B + (long)row_ * 256 + (kc) + col8_, true);                      \
        }                                                                         \
        cp_commit();                                                              \
    }

    LOAD_STAGE(0, 0);
    const int arow = mw + (lane & 15);
    const int brow = nw + (lane & 15);
    const int acol = (lane >> 4) * 8;

#pragma unroll 1
    for (int ch = 0; ch < 4; ch++) {
        if (ch < 3) { LOAD_STAGE((ch + 1) & 1, (ch + 1) * 64); }
        if (ch < 3) asm volatile("cp.async.wait_group 1;");
        else        asm volatile("cp.async.wait_group 0;");
        __syncthreads();
        uint32_t sA = smb + (ch & 1) * 36864;
        uint32_t sB = sA + 18432;
#pragma unroll
        for (int ks = 0; ks < 4; ks++) {
            int k0 = ks * 16;
            uint32_t af[2][4];
#pragma unroll
            for (int i = 0; i < 2; i++)
                ldmx4(af[i], sA + ((arow + i * 16) * LDSW + k0 + acol) * 2);
#pragma unroll
            for (int j2 = 0; j2 < 4; j2++) {
                uint32_t t[4];
                ldmx4(t, sB + ((brow + j2 * 16) * LDSW + k0 + acol) * 2);
#pragma unroll
                for (int i = 0; i < 2; i++) {
                    mma16816(acc[i][2 * j2],     af[i], t[0], t[2]);
                    mma16816(acc[i][2 * j2 + 1], af[i], t[1], t[3]);
                }
            }
        }
        __syncthreads();
    }

    const int r_in = lane >> 2;
    const int cpair = (lane & 3) * 2;
#pragma unroll
    for (int i = 0; i < 2; i++) {
        long gm = m0 + mw + i * 16 + r_in;
#pragma unroll
        for (int j = 0; j < 8; j++) {
            int colg = nw + j * 8 + cpair;
            float2 v0 = make_float2(acc[i][j][0], acc[i][j][1]);
            float2 v1 = make_float2(acc[i][j][2], acc[i][j][3]);
            if (EPI == 1) {
                float bx = bias[colg], by = bias[colg + 1];
                v0.x = leaky(v0.x + bx); v0.y = leaky(v0.y + by);
                v1.x = leaky(v1.x + bx); v1.y = leaky(v1.y + by);
            }
            if (gm < N_NODES)     *(float2*)&C[gm * 128 + colg] = v0;
            if (gm + 8 < N_NODES) *(float2*)&C[(gm + 8) * 128 + colg] = v1;
        }
    }
#undef LOAD_STAGE
}

// ---------------- fused gates GEMM + GRU ----------------
// Per CTA: 64 rows x 384 gate-cols. Logical blocks: 0=r_sum, 1=z_sum, 2=i_n, 3=h_n.
// Phase 0 (chunks 0-3): A=mext, B=Wih -> blocks {0,1,2}
// Phase 1 (chunks 4-7): A=gext, B=Whh -> blocks {0,1,3}
// Epilogue: GRU update -> Gb (fp32) + gext ([hi|lo]).
__global__ void __launch_bounds__(512) k_gates(
    const __half* __restrict__ mext, __half* gext,
    const __half* __restrict__ wih, const __half* __restrict__ whh,
    const float* __restrict__ b_ih, const float* __restrict__ b_hh,
    float* __restrict__ Gb)
{
    extern __shared__ __align__(16) char smraw[];
    uint32_t smb = smem_u32(smraw);
    const int tid = threadIdx.x, lane = tid & 31, w = tid >> 5;
    const int mwarp = w & 1;          // 32-row half
    const int nwarp = w >> 1;         // 16-col slice within each 128-block
    const long m0 = (long)blockIdx.x * 64;

    float acc[2][4][2][4];
#pragma unroll
    for (int i = 0; i < 2; i++)
#pragma unroll
        for (int b = 0; b < 4; b++)
#pragma unroll
            for (int j = 0; j < 2; j++)
#pragma unroll
                for (int e = 0; e < 4; e++) acc[i][b][j][e] = 0.f;

#define GLOAD(st, c)                                                              \
    {                                                                             \
        int p_ = (c) >> 2, kc_ = ((c) & 3) * 64;                                  \
        const __half* As_ = p_ ? gext : mext;                                     \
        const __half* Bs_ = p_ ? whh : wih;                                       \
        uint32_t aA = smb + (st) * 64512;                                         \
        uint32_t aB = aA + 9216;                                                  \
        {                                                                         \
            int r_ = tid >> 3, c8_ = (tid & 7) * 8;                               \
            long gr_ = m0 + r_;                                                   \
            bool v_ = gr_ < N_NODES;                                              \
            cp16(aA + (r_ * LDSW + c8_) * 2,                                      \
                 As_ + (v_ ? gr_ * 256 + kc_ + c8_ : 0), v_);                     \
        }                                                                         \
        _Pragma("unroll")                                                         \
        for (int i_ = 0; i_ < 6; i_++) {                                          \
            int cc_ = tid + i_ * 512;                                             \
            int r_ = cc_ >> 3, c8_ = (cc_ & 7) * 8;                               \
            cp16(aB + (r_ * LDSW + c8_) * 2,                                      \
                 Bs_ + (long)r_ * 256 + kc_ + c8_, true);                         \
        }                                                                         \
        cp_commit();                                                              \
    }

    GLOAD(0, 0);
    const int arow = mwarp * 32 + (lane & 15);
    const int brow = nwarp * 16 + (lane & 15);
    const int acol = (lane >> 4) * 8;

#pragma unroll
    for (int ph = 0; ph < 2; ph++) {
#pragma unroll 1
        for (int cc = 0; cc < 4; cc++) {
            int t = ph * 4 + cc;
            if (t < 7) { GLOAD((t + 1) & 1, t + 1); }
            if (t < 7) asm volatile("cp.async.wait_group 1;");
            else       asm volatile("cp.async.wait_group 0;");
            __syncthreads();
            uint32_t sA = smb + (t & 1) * 64512;
            uint32_t sB = sA + 9216;
#pragma unroll
            for (int ks = 0; ks < 4; ks++) {
                int k0 = ks * 16;
                uint32_t af[2][4];
#pragma unroll
                for (int i = 0; i < 2; i++)
                    ldmx4(af[i], sA + ((arow + i * 16) * LDSW + k0 + acol) * 2);
#pragma unroll
                for (int sb = 0; sb < 3; sb++) {
                    const int lb = (ph == 0) ? sb : (sb == 2 ? 3 : sb);
                    uint32_t bt[4];
                    ldmx4(bt, sB + ((sb * 128 + brow) * LDSW + k0 + acol) * 2);
#pragma unroll
                    for (int i = 0; i < 2; i++) {
                        mma16816(acc[i][lb][0], af[i], bt[0], bt[2]);
                        mma16816(acc[i][lb][1], af[i], bt[1], bt[3]);
                    }
                }
            }
            __syncthreads();
        }
    }

    // ---- fused GRU epilogue ----
    const int r_in = lane >> 2;
    const int cpair = (lane & 3) * 2;
#pragma unroll
    for (int i = 0; i < 2; i++) {
#pragma unroll
        for (int hrow = 0; hrow < 2; hrow++) {
            long gm = m0 + mwarp * 32 + i * 16 + r_in + hrow * 8;
            if (gm >= N_NODES) continue;
#pragma unroll
            for (int j = 0; j < 2; j++) {
                int c = nwarp * 16 + j * 8 + cpair;   // 0..127
                float g2[2];
#pragma unroll
                for (int e = 0; e < 2; e++) {
                    int cc = c + e;
                    float rs = acc[i][0][j][hrow * 2 + e] + b_ih[cc] + b_hh[cc];
                    float zs = acc[i][1][j][hrow * 2 + e] + b_ih[128 + cc] + b_hh[128 + cc];
                    float in_ = acc[i][2][j][hrow * 2 + e] + b_ih[256 + cc];
                    float hn  = acc[i][3][j][hrow * 2 + e] + b_hh[256 + cc];
                    float r = sigm(rs), z = sigm(zs);
                    float n = tanhf(in_ + r * hn);
                    float go = Gb[gm * 128 + cc];
                    g2[e] = (1.f - z) * n + z * go;
                }
                *(float2*)&Gb[gm * 128 + c] = make_float2(g2[0], g2[1]);
                st_splitA2(gext + gm * 256 + c, g2[0], g2[1]);
            }
        }
    }
#undef GLOAD
}

// ---------------- aggregation (pull-CSR, warp per node) ----------------
__global__ void k_gcn_agg(const float* __restrict__ bias) {
    int v = blockIdx.x * 8 + (threadIdx.x >> 5);
    if (v >= N_NODES) return;
    int lane = threadIdx.x & 31;
    const float4* x4 = (const float4*)d_XW;
    float4 acc = make_float4(0.f, 0.f, 0.f, 0.f);
    float dv = d_dinv[v];
    int s = d_off[v], e = d_off[v + 1];
    for (int i = s; i < e; i++) {
        int u = d_csr[i];
        float c = d_dinv[u] * dv;
        float4 t = x4[(long)u * 32 + lane];
        acc.x += t.x * c; acc.y += t.y * c; acc.z += t.z * c; acc.w += t.w * c;
    }
    float4 slf = x4[(long)v * 32 + lane];
    float sc = dv * dv;
    float4 b = ((const float4*)bias)[lane];
    acc.x = leaky(acc.x + slf.x * sc + b.x);
    acc.y = leaky(acc.y + slf.y * sc + b.y);
    acc.z = leaky(acc.z + slf.z * sc + b.z);
    acc.w = leaky(acc.w + slf.w * sc + b.w);
    ((float4*)d_Hb)[(long)v * 32 + lane] = acc;
    ((float4*)d_Gb)[(long)v * 32 + lane] = acc;
    st_splitA(d_gext + (long)v * 256 + lane * 4, acc);
}

__global__ void k_gg_agg() {
    int v = blockIdx.x * 8 + (threadIdx.x >> 5);
    if (v >= N_NODES) return;
    int lane = threadIdx.x & 31;
    const float4* x4 = (const float4*)d_XW;
    float4 acc = make_float4(0.f, 0.f, 0.f, 0.f);
    int s = d_off[v], e = d_off[v + 1];
    for (int i = s; i < e; i++) {
        int u = d_csr[i];
        float4 t = x4[(long)u * 32 + lane];
        acc.x += t.x; acc.y += t.y; acc.z += t.z; acc.w += t.w;
    }
    st_splitA(d_mext + (long)v * 256 + lane * 4, acc);
}

// ---------------- head / elementwise ----------------
__global__ void k_resid() {
    long idx = (long)blockIdx.x * 256 + threadIdx.x;
    if (idx >= 1600000L) return;
    float4 g = ((const float4*)d_Gb)[idx];
    float4 hh = ((const float4*)d_Hb)[idx];
    float4 t;
    t.x = leaky(g.x) + hh.x; t.y = leaky(g.y) + hh.y;
    t.z = leaky(g.z) + hh.z; t.w = leaky(g.w) + hh.w;
    long v = idx >> 5; int q = (int)(idx & 31);
    st_splitA(d_hext + v * 256 + q * 4, t);
}

__global__ void k_probs(const float* __restrict__ W2, const float* __restrict__ b2) {
    int v = blockIdx.x * 8 + (threadIdx.x >> 5);
    if (v >= N_NODES) return;
    int lane = threadIdx.x & 31;
    float4 tv = ((const float4*)d_XW)[(long)v * 32 + lane];
    float4 wv = ((const float4*)W2)[lane];
    float s = tv.x * wv.x + tv.y * wv.y + tv.z * wv.z + tv.w * wv.w;
#pragma unroll
    for (int o = 16; o; o >>= 1) s += __shfl_xor_sync(0xffffffffu, s, o);
    if (lane == 0) d_probs[v] = sigm(s + b2[0]);
}

// ---------------- loss ----------------
__global__ void k_loss_nodes(const int* __restrict__ batch, float* __restrict__ out) {
    __shared__ float sm[NGRAPH];
    if (threadIdx.x < NGRAPH) sm[threadIdx.x] = 0.f;
    __syncthreads();
    for (int v = blockIdx.x * blockDim.x + threadIdx.x; v < N_NODES;
         v += gridDim.x * blockDim.x)
        atomicAdd(&sm[batch[v]], -0.5f * d_probs[v] * (float)d_degr[v]);
    __syncthreads();
    if (threadIdx.x < NGRAPH) atomicAdd(&out[threadIdx.x], sm[threadIdx.x]);
}
__global__ void k_loss_edges(const int* __restrict__ row, const int* __restrict__ col,
                             const int* __restrict__ batch, float* __restrict__ out) {
    __shared__ float sm[NGRAPH];
    if (threadIdx.x < NGRAPH) sm[threadIdx.x] = 0.f;
    __syncthreads();
    for (int e = blockIdx.x * blockDim.x + threadIdx.x; e < N_EDGES;
         e += gridDim.x * blockDim.x) {
        int r = row[e];
        atomicAdd(&sm[batch[r]], 0.5f * d_probs[r] * d_probs[col[e]]);
    }
    __syncthreads();
    if (threadIdx.x < NGRAPH) atomicAdd(&out[threadIdx.x], sm[threadIdx.x]);
}

// ---------------- launch ----------------
extern "C" void kernel_launch(void* const* d_in, const int* in_sizes, int n_in,
                              void* d_out, int out_size)
{
    const float* x     = (const float*)d_in[0];
    const int*   ei    = (const int*)d_in[1];
    const int*   batch = (const int*)d_in[2];
    const float* W_gcn = (const float*)d_in[3];
    const float* b_gcn = (const float*)d_in[4];
    const float* W_gg  = (const float*)d_in[5];
    const float* W_ih  = (const float*)d_in[6];
    const float* W_hh  = (const float*)d_in[7];
    const float* b_ih  = (const float*)d_in[8];
    const float* b_hh  = (const float*)d_in[9];
    const float* W1    = (const float*)d_in[10];
    const float* b1    = (const float*)d_in[11];
    const float* W2    = (const float*)d_in[12];
    const float* b2    = (const float*)d_in[13];
    float* out = (float*)d_out;
    const int* row = ei;
    const int* col = ei + N_EDGES;

    const int SMEM = 2 * 36864;    // k_mm double buffer
    const int SMG  = 2 * 64512;    // k_gates double buffer (129 KB)
    cudaFuncSetAttribute(k_mm<0>, cudaFuncAttributeMaxDynamicSharedMemorySize, SMEM);
    cudaFuncSetAttribute(k_mm<1>, cudaFuncAttributeMaxDynamicSharedMemorySize, SMEM);
    cudaFuncSetAttribute(k_gates, cudaFuncAttributeMaxDynamicSharedMemorySize, SMG);

    __half *xext, *gext, *mext, *hext, *wext;
    float *XW, *Gb;
    cudaGetSymbolAddress((void**)&xext, d_xext);
    cudaGetSymbolAddress((void**)&gext, d_gext);
    cudaGetSymbolAddress((void**)&mext, d_mext);
    cudaGetSymbolAddress((void**)&hext, d_hext);
    cudaGetSymbolAddress((void**)&wext, d_wext);
    cudaGetSymbolAddress((void**)&XW, d_XW);
    cudaGetSymbolAddress((void**)&Gb, d_Gb);

    // CSR build + operand splits
    k_zero<<<196, 256>>>(out);
    k_count<<<3125, 256>>>(row, col);
    k_dinv<<<196, 256>>>();
    k_scan1<<<196, 256>>>();
    k_scan2<<<1, 256>>>();
    k_scan3<<<196, 256>>>();
    k_scatter<<<3125, 256>>>(row, col);
    k_split_x<<<6250, 256>>>(x);
    k_split_w<<<704, 256>>>(W_gcn, W_gg, W_ih, W_hh, W1);

    // GCN
    k_mm<0><<<MTILES, 256, SMEM>>>(xext, wext, nullptr, XW);
    k_gcn_agg<<<6250, 256>>>(b_gcn);

    // 3x GatedGraphConv + fused gates/GRU
    for (int l = 0; l < 3; l++) {
        k_mm<0><<<MTILES, 256, SMEM>>>(gext, wext + (long)(128 + 128 * l) * 256,
                                       nullptr, XW);
        k_gg_agg<<<6250, 256>>>();
        k_gates<<<782, 512, SMG>>>(mext, gext, wext + 512L * 256, wext + 896L * 256,
                                   b_ih, b_hh, Gb);
    }

    // head
    k_resid<<<6250, 256>>>();
    k_mm<1><<<MTILES, 256, SMEM>>>(hext, wext + 1280L * 256, b1, XW);
    k_probs<<<6250, 256>>>(W2, b2);

    // loss
    k_loss_nodes<<<512, 256>>>(batch, out);
    k_loss_edges<<<512, 256>>>(row, col, batch, out);
}

// round 11
// speedup vs baseline: 2.4826x; 1.2733x over previous
#include <cuda_runtime.h>
#include <cuda_fp16.h>
#include <math.h>
#include <stdint.h>

#define N_NODES 50000
#define N_EDGES 800000
#define NGRAPH  64
#define NEG     0.01f
#define MTILES  391   // ceil(50000/128)
#define LDSW    72    // padded smem row stride (half) = 144B

// ---------------- device globals ----------------
__device__ float d_XW[6400000];      // fp32 head output (for k_probs)
__device__ float d_Hb[6400000];      // residual h (fp32)
__device__ float d_Gb[6400000];      // GRU state (fp32)
__device__ __half d_xh[6400000];     // x quantized
__device__ __half d_gh[6400000];     // g quantized (GEMM/gather operand)
__device__ __half d_mh[6400000];     // aggregated message
__device__ __half d_hh[6400000];     // resid output
__device__ __half d_XWh[6400000];    // GCN xw (fp16, gathered)
// weight rows [n][k] (B[n][k] = sum_k A[m][k]B[n][k]):
//  0..127   Wgcn^T | 128+l*384.. Wc[l]=Wgg[l]@WihT | 1280..1663 Whh | 1664..1791 W1^T
__device__ __half d_wh[229376];
__device__ float d_dinv[N_NODES];
__device__ float d_probs[N_NODES];
__device__ int d_degc[N_NODES];
__device__ int d_degr[N_NODES];
__device__ int d_fill[N_NODES];
__device__ int d_off[N_NODES + 1];
__device__ int d_csr[N_EDGES];
__device__ int d_bsum[256];

__device__ __forceinline__ float leaky(float x) { return x > 0.f ? x : NEG * x; }
__device__ __forceinline__ float sigm(float x)  { return 1.f / (1.f + __expf(-x)); }

__device__ __forceinline__ uint32_t smem_u32(const void* p) {
    uint32_t a;
    asm("{ .reg .u64 t; cvta.to.shared.u64 t, %1; cvt.u32.u64 %0, t; }" : "=r"(a) : "l"(p));
    return a;
}
__device__ __forceinline__ void cp16(uint32_t dst, const void* src, bool valid) {
    int sz = valid ? 16 : 0;
    asm volatile("cp.async.cg.shared.global [%0], [%1], 16, %2;"
                 :: "r"(dst), "l"(src), "r"(sz));
}
__device__ __forceinline__ void cp_commit() { asm volatile("cp.async.commit_group;"); }
__device__ __forceinline__ void ldmx4(uint32_t* r, uint32_t addr) {
    asm volatile("ldmatrix.sync.aligned.m8n8.x4.shared.b16 {%0,%1,%2,%3}, [%4];"
                 : "=r"(r[0]), "=r"(r[1]), "=r"(r[2]), "=r"(r[3]) : "r"(addr));
}
__device__ __forceinline__ void mma16816(float* c, const uint32_t* a, uint32_t b0, uint32_t b1) {
    asm volatile(
        "mma.sync.aligned.m16n8k16.row.col.f32.f16.f16.f32 "
        "{%0,%1,%2,%3}, {%4,%5,%6,%7}, {%8,%9}, {%0,%1,%2,%3};"
        : "+f"(c[0]), "+f"(c[1]), "+f"(c[2]), "+f"(c[3])
        : "r"(a[0]), "r"(a[1]), "r"(a[2]), "r"(a[3]), "r"(b0), "r"(b1));
}
__device__ __forceinline__ uint32_t pack4(float a, float b, float c, float d, uint32_t* hi) {
    __half2 h0 = __floats2half2_rn(a, b);
    __half2 h1 = __floats2half2_rn(c, d);
    *hi = *(uint32_t*)&h1;
    return *(uint32_t*)&h0;
}

// ---------------- CSR build ----------------
__global__ void k_zero(float* out) {
    int i = blockIdx.x * blockDim.x + threadIdx.x;
    if (i < N_NODES) { d_degc[i] = 0; d_degr[i] = 0; d_fill[i] = 0; }
    if (i < NGRAPH) out[i] = 0.f;
}
__global__ void k_count(const int* __restrict__ row, const int* __restrict__ col) {
    int e = blockIdx.x * blockDim.x + threadIdx.x;
    if (e < N_EDGES) { atomicAdd(&d_degc[col[e]], 1); atomicAdd(&d_degr[row[e]], 1); }
}
__global__ void k_dinv() {
    int i = blockIdx.x * blockDim.x + threadIdx.x;
    if (i < N_NODES) d_dinv[i] = rsqrtf((float)d_degc[i] + 1.f);
}
__global__ void k_scan1() {
    __shared__ int sm[256];
    int i = blockIdx.x * 256 + threadIdx.x;
    sm[threadIdx.x] = (i < N_NODES) ? d_degc[i] : 0;
    __syncthreads();
    for (int o = 128; o; o >>= 1) {
        if (threadIdx.x < o) sm[threadIdx.x] += sm[threadIdx.x + o];
        __syncthreads();
    }
    if (threadIdx.x == 0) d_bsum[blockIdx.x] = sm[0];
}
__global__ void k_scan2() {
    __shared__ int sm[256];
    int t = threadIdx.x;
    int v = (t < 196) ? d_bsum[t] : 0;
    sm[t] = v; __syncthreads();
    for (int o = 1; o < 256; o <<= 1) {
        int x = (t >= o) ? sm[t - o] : 0;
        __syncthreads(); sm[t] += x; __syncthreads();
    }
    if (t < 196) d_bsum[t] = sm[t] - v;
    if (t == 0) d_off[N_NODES] = N_EDGES;
}
__global__ void k_scan3() {
    __shared__ int sm[256];
    int t = threadIdx.x, i = blockIdx.x * 256 + t;
    int v = (i < N_NODES) ? d_degc[i] : 0;
    sm[t] = v; __syncthreads();
    for (int o = 1; o < 256; o <<= 1) {
        int x = (t >= o) ? sm[t - o] : 0;
        __syncthreads(); sm[t] += x; __syncthreads();
    }
    if (i < N_NODES) d_off[i] = d_bsum[blockIdx.x] + sm[t] - v;
}
__global__ void k_scatter(const int* __restrict__ row, const int* __restrict__ col) {
    int e = blockIdx.x * blockDim.x + threadIdx.x;
    if (e < N_EDGES) {
        int c = col[e];
        d_csr[d_off[c] + atomicAdd(&d_fill[c], 1)] = row[e];
    }
}

// ---------------- weight prep ----------------
__global__ void k_quant_x(const float* __restrict__ x) {
    long idx = (long)blockIdx.x * 256 + threadIdx.x;
    if (idx >= 1600000L) return;
    float4 v = ((const float4*)x)[idx];
    uint32_t hi, lo = pack4(v.x, v.y, v.z, v.w, &hi);
    ((uint2*)d_xh)[idx] = make_uint2(lo, hi);
}
// direct-quantized weights (Wgcn^T, Whh, W1^T)
__global__ void k_wq(const float* __restrict__ Wgcn, const float* __restrict__ Whh,
                     const float* __restrict__ W1) {
    int idx = blockIdx.x * 256 + threadIdx.x;
    if (idx >= 640 * 128) return;
    int r = idx >> 7, k = idx & 127;
    float v; long dr;
    if (r < 128)      { v = Wgcn[k * 128 + r];        dr = r; }
    else if (r < 512) { int n = r - 128; v = Whh[n * 128 + k]; dr = 1280 + n; }
    else              { int n = r - 512; v = W1[k * 128 + n];  dr = 1664 + n; }
    d_wh[dr * 128 + k] = __float2half_rn(v);
}
// Wc[l][j][n] = sum_c Wgg[l][j][c] * Wih[n][c];  B row n: B[n][j]=Wc[l][j][n]
__global__ void k_wc(const float* __restrict__ Wgg, const float* __restrict__ Wih) {
    int b = blockIdx.x;            // 0..1151
    int l = b / 384, n = b % 384;
    __shared__ float s[128];
    s[threadIdx.x] = Wih[n * 128 + threadIdx.x];
    __syncthreads();
    const float* wg = Wgg + (long)l * 16384 + threadIdx.x * 128;  // row j = tid
    float acc = 0.f;
#pragma unroll 8
    for (int c = 0; c < 128; c++) acc += wg[c] * s[c];
    d_wh[(long)(128 + l * 384 + n) * 128 + threadIdx.x] = __float2half_rn(acc);
}

// ---------------- fp16 HMMA GEMM, K=128 ----------------
// C[m][n] = sum_k A[m][k] * B[n][k].  EPI 0: half out.  EPI 1: fp32 bias+leaky out.
template <int EPI>
__global__ void __launch_bounds__(256) k_mm(
    const __half* __restrict__ A, const __half* __restrict__ B,
    const float* __restrict__ bias, void* __restrict__ Cv)
{
    extern __shared__ __align__(16) char smraw[];
    uint32_t smb = smem_u32(smraw);
    const int tid = threadIdx.x, lane = tid & 31, wid = tid >> 5;
    const int mw = (wid >> 1) * 32;
    const int nw = (wid & 1) * 64;
    const long m0 = (long)blockIdx.x * 128;

    float acc[2][8][4];
#pragma unroll
    for (int i = 0; i < 2; i++)
#pragma unroll
        for (int j = 0; j < 8; j++)
#pragma unroll
            for (int e = 0; e < 4; e++) acc[i][j][e] = 0.f;

#define LOAD_STAGE(st, kc)                                                        \
    {                                                                             \
        uint32_t aA = smb + (st) * 36864;                                         \
        uint32_t aB = aA + 18432;                                                 \
        _Pragma("unroll")                                                         \
        for (int i_ = 0; i_ < 4; i_++) {                                          \
            int c_ = tid + i_ * 256;                                              \
            int row_ = c_ >> 3, col8_ = (c_ & 7) * 8;                             \
            long gr_ = m0 + row_;                                                 \
            bool v_ = gr_ < N_NODES;                                              \
            cp16(aA + (row_ * LDSW + col8_) * 2,                                  \
                 A + (v_ ? gr_ * 128 + (kc) + col8_ : 0), v_);                    \
            cp16(aB + (row_ * LDSW + col8_) * 2,                                  \
                 B + (long)row_ * 128 + (kc) + col8_, true);                      \
        }                                                                         \
        cp_commit();                                                              \
    }

    LOAD_STAGE(0, 0);
    const int arow = mw + (lane & 15);
    const int brow = nw + (lane & 15);
    const int acol = (lane >> 4) * 8;

#pragma unroll 1
    for (int ch = 0; ch < 2; ch++) {
        if (ch < 1) { LOAD_STAGE(1, 64); }
        if (ch < 1) asm volatile("cp.async.wait_group 1;");
        else        asm volatile("cp.async.wait_group 0;");
        __syncthreads();
        uint32_t sA = smb + (ch & 1) * 36864;
        uint32_t sB = sA + 18432;
#pragma unroll
        for (int ks = 0; ks < 4; ks++) {
            int k0 = ks * 16;
            uint32_t af[2][4];
#pragma unroll
            for (int i = 0; i < 2; i++)
                ldmx4(af[i], sA + ((arow + i * 16) * LDSW + k0 + acol) * 2);
#pragma unroll
            for (int j2 = 0; j2 < 4; j2++) {
                uint32_t t[4];
                ldmx4(t, sB + ((brow + j2 * 16) * LDSW + k0 + acol) * 2);
#pragma unroll
                for (int i = 0; i < 2; i++) {
                    mma16816(acc[i][2 * j2],     af[i], t[0], t[2]);
                    mma16816(acc[i][2 * j2 + 1], af[i], t[1], t[3]);
                }
            }
        }
        __syncthreads();
    }

    const int r_in = lane >> 2;
    const int cpair = (lane & 3) * 2;
#pragma unroll
    for (int i = 0; i < 2; i++) {
        long gm = m0 + mw + i * 16 + r_in;
#pragma unroll
        for (int j = 0; j < 8; j++) {
            int colg = nw + j * 8 + cpair;
            if (EPI == 0) {
                __half* C = (__half*)Cv;
                __half2 h0 = __floats2half2_rn(acc[i][j][0], acc[i][j][1]);
                __half2 h1 = __floats2half2_rn(acc[i][j][2], acc[i][j][3]);
                if (gm < N_NODES)     *(__half2*)&C[gm * 128 + colg] = h0;
                if (gm + 8 < N_NODES) *(__half2*)&C[(gm + 8) * 128 + colg] = h1;
            } else {
                float* C = (float*)Cv;
                float bx = bias[colg], by = bias[colg + 1];
                float2 v0 = make_float2(leaky(acc[i][j][0] + bx), leaky(acc[i][j][1] + by));
                float2 v1 = make_float2(leaky(acc[i][j][2] + bx), leaky(acc[i][j][3] + by));
                if (gm < N_NODES)     *(float2*)&C[gm * 128 + colg] = v0;
                if (gm + 8 < N_NODES) *(float2*)&C[(gm + 8) * 128 + colg] = v1;
            }
        }
    }
#undef LOAD_STAGE
}

// ---------------- fused gates GEMM + GRU (K=128 per phase) ----------------
// Blocks: 0=r_sum, 1=z_sum, 2=i_n, 3=h_n.
// Phase 0 (chunks 0-1): A=mh, B=Wc[l]  -> {0,1,2}
// Phase 1 (chunks 2-3): A=gh, B=Whh    -> {0,1,3}
__global__ void __launch_bounds__(512) k_gates(
    const __half* __restrict__ mh, __half* gh,
    const __half* __restrict__ wc, const __half* __restrict__ whh,
    const float* __restrict__ b_ih, const float* __restrict__ b_hh,
    float* __restrict__ Gb)
{
    extern __shared__ __align__(16) char smraw[];
    uint32_t smb = smem_u32(smraw);
    const int tid = threadIdx.x, lane = tid & 31, w = tid >> 5;
    const int mwarp = w & 1;
    const int nwarp = w >> 1;
    const long m0 = (long)blockIdx.x * 64;

    float acc[2][4][2][4];
#pragma unroll
    for (int i = 0; i < 2; i++)
#pragma unroll
        for (int b = 0; b < 4; b++)
#pragma unroll
            for (int j = 0; j < 2; j++)
#pragma unroll
                for (int e = 0; e < 4; e++) acc[i][b][j][e] = 0.f;

#define GLOAD(st, c)                                                              \
    {                                                                             \
        int p_ = (c) >> 1, kc_ = ((c) & 1) * 64;                                  \
        const __half* As_ = p_ ? gh : mh;                                         \
        const __half* Bs_ = p_ ? whh : wc;                                        \
        uint32_t aA = smb + (st) * 64512;                                         \
        uint32_t aB = aA + 9216;                                                  \
        {                                                                         \
            int r_ = tid >> 3, c8_ = (tid & 7) * 8;                               \
            long gr_ = m0 + r_;                                                   \
            bool v_ = gr_ < N_NODES;                                              \
            cp16(aA + (r_ * LDSW + c8_) * 2,                                      \
                 As_ + (v_ ? gr_ * 128 + kc_ + c8_ : 0), v_);                     \
        }                                                                         \
        _Pragma("unroll")                                                         \
        for (int i_ = 0; i_ < 6; i_++) {                                          \
            int cc_ = tid + i_ * 512;                                             \
            int r_ = cc_ >> 3, c8_ = (cc_ & 7) * 8;                               \
            cp16(aB + (r_ * LDSW + c8_) * 2,                                      \
                 Bs_ + (long)r_ * 128 + kc_ + c8_, true);                         \
        }                                                                         \
        cp_commit();                                                              \
    }

    GLOAD(0, 0);
    const int arow = mwarp * 32 + (lane & 15);
    const int brow = nwarp * 16 + (lane & 15);
    const int acol = (lane >> 4) * 8;

#pragma unroll 1
    for (int t = 0; t < 4; t++) {
        if (t < 3) { GLOAD((t + 1) & 1, t + 1); }
        if (t < 3) asm volatile("cp.async.wait_group 1;");
        else       asm volatile("cp.async.wait_group 0;");
        __syncthreads();
        int ph = t >> 1;
        uint32_t sA = smb + (t & 1) * 64512;
        uint32_t sB = sA + 9216;
#pragma unroll
        for (int ks = 0; ks < 4; ks++) {
            int k0 = ks * 16;
            uint32_t af[2][4];
#pragma unroll
            for (int i = 0; i < 2; i++)
                ldmx4(af[i], sA + ((arow + i * 16) * LDSW + k0 + acol) * 2);
#pragma unroll
            for (int sb = 0; sb < 3; sb++) {
                const int lb = (ph == 0) ? sb : (sb == 2 ? 3 : sb);
                uint32_t bt[4];
                ldmx4(bt, sB + ((sb * 128 + brow) * LDSW + k0 + acol) * 2);
#pragma unroll
                for (int i = 0; i < 2; i++) {
                    mma16816(acc[i][lb][0], af[i], bt[0], bt[2]);
                    mma16816(acc[i][lb][1], af[i], bt[1], bt[3]);
                }
            }
        }
        __syncthreads();
    }

    const int r_in = lane >> 2;
    const int cpair = (lane & 3) * 2;
#pragma unroll
    for (int i = 0; i < 2; i++) {
#pragma unroll
        for (int hrow = 0; hrow < 2; hrow++) {
            long gm = m0 + mwarp * 32 + i * 16 + r_in + hrow * 8;
            if (gm >= N_NODES) continue;
#pragma unroll
            for (int j = 0; j < 2; j++) {
                int c = nwarp * 16 + j * 8 + cpair;
                float g2[2];
#pragma unroll
                for (int e = 0; e < 2; e++) {
                    int cc = c + e;
                    float rs = acc[i][0][j][hrow * 2 + e] + b_ih[cc] + b_hh[cc];
                    float zs = acc[i][1][j][hrow * 2 + e] + b_ih[128 + cc] + b_hh[128 + cc];
                    float in_ = acc[i][2][j][hrow * 2 + e] + b_ih[256 + cc];
                    float hn  = acc[i][3][j][hrow * 2 + e] + b_hh[256 + cc];
                    float r = sigm(rs), z = sigm(zs);
                    float n = tanhf(in_ + r * hn);
                    g2[e] = (1.f - z) * n + z * Gb[gm * 128 + cc];
                }
                *(float2*)&Gb[gm * 128 + c] = make_float2(g2[0], g2[1]);
                *(__half2*)&gh[gm * 128 + c] = __floats2half2_rn(g2[0], g2[1]);
            }
        }
    }
#undef GLOAD
}

// ---------------- aggregation (pull-CSR, warp/node, fp16 features) ----------------
__device__ __forceinline__ float4 h4tof4(uint2 p) {
    __half2 a = *(__half2*)&p.x, b = *(__half2*)&p.y;
    float2 fa = __half22float2(a), fb = __half22float2(b);
    return make_float4(fa.x, fa.y, fb.x, fb.y);
}

__global__ void k_gcn_agg(const float* __restrict__ bias) {
    int v = blockIdx.x * 8 + (threadIdx.x >> 5);
    if (v >= N_NODES) return;
    int lane = threadIdx.x & 31;
    const uint2* x2 = (const uint2*)d_XWh;
    float4 acc = make_float4(0.f, 0.f, 0.f, 0.f);
    float dv = d_dinv[v];
    int s = d_off[v], e = d_off[v + 1];
    for (int i = s; i < e; i++) {
        int u = d_csr[i];
        float c = d_dinv[u] * dv;
        float4 t = h4tof4(x2[(long)u * 32 + lane]);
        acc.x += t.x * c; acc.y += t.y * c; acc.z += t.z * c; acc.w += t.w * c;
    }
    float4 slf = h4tof4(x2[(long)v * 32 + lane]);
    float sc = dv * dv;
    float4 b = ((const float4*)bias)[lane];
    acc.x = leaky(acc.x + slf.x * sc + b.x);
    acc.y = leaky(acc.y + slf.y * sc + b.y);
    acc.z = leaky(acc.z + slf.z * sc + b.z);
    acc.w = leaky(acc.w + slf.w * sc + b.w);
    ((float4*)d_Hb)[(long)v * 32 + lane] = acc;
    ((float4*)d_Gb)[(long)v * 32 + lane] = acc;
    uint32_t hi, lo = pack4(acc.x, acc.y, acc.z, acc.w, &hi);
    ((uint2*)d_gh)[(long)v * 32 + lane] = make_uint2(lo, hi);
}

__global__ void k_gg_agg() {
    int v = blockIdx.x * 8 + (threadIdx.x >> 5);
    if (v >= N_NODES) return;
    int lane = threadIdx.x & 31;
    const uint2* g2 = (const uint2*)d_gh;
    float4 acc = make_float4(0.f, 0.f, 0.f, 0.f);
    int s = d_off[v], e = d_off[v + 1];
    for (int i = s; i < e; i++) {
        int u = d_csr[i];
        float4 t = h4tof4(g2[(long)u * 32 + lane]);
        acc.x += t.x; acc.y += t.y; acc.z += t.z; acc.w += t.w;
    }
    uint32_t hi, lo = pack4(acc.x, acc.y, acc.z, acc.w, &hi);
    ((uint2*)d_mh)[(long)v * 32 + lane] = make_uint2(lo, hi);
}

// ---------------- head / elementwise ----------------
__global__ void k_resid() {
    long idx = (long)blockIdx.x * 256 + threadIdx.x;
    if (idx >= 1600000L) return;
    float4 g = ((const float4*)d_Gb)[idx];
    float4 hh = ((const float4*)d_Hb)[idx];
    uint32_t hi, lo = pack4(leaky(g.x) + hh.x, leaky(g.y) + hh.y,
                            leaky(g.z) + hh.z, leaky(g.w) + hh.w, &hi);
    ((uint2*)d_hh)[idx] = make_uint2(lo, hi);
}

__global__ void k_probs(const float* __restrict__ W2, const float* __restrict__ b2) {
    int v = blockIdx.x * 8 + (threadIdx.x >> 5);
    if (v >= N_NODES) return;
    int lane = threadIdx.x & 31;
    float4 tv = ((const float4*)d_XW)[(long)v * 32 + lane];
    float4 wv = ((const float4*)W2)[lane];
    float s = tv.x * wv.x + tv.y * wv.y + tv.z * wv.z + tv.w * wv.w;
#pragma unroll
    for (int o = 16; o; o >>= 1) s += __shfl_xor_sync(0xffffffffu, s, o);
    if (lane == 0) d_probs[v] = sigm(s + b2[0]);
}

// ---------------- loss ----------------
__global__ void k_loss_nodes(const int* __restrict__ batch, float* __restrict__ out) {
    __shared__ float sm[NGRAPH];
    if (threadIdx.x < NGRAPH) sm[threadIdx.x] = 0.f;
    __syncthreads();
    for (int v = blockIdx.x * blockDim.x + threadIdx.x; v < N_NODES;
         v += gridDim.x * blockDim.x)
        atomicAdd(&sm[batch[v]], -0.5f * d_probs[v] * (float)d_degr[v]);
    __syncthreads();
    if (threadIdx.x < NGRAPH) atomicAdd(&out[threadIdx.x], sm[threadIdx.x]);
}
__global__ void k_loss_edges(const int* __restrict__ row, const int* __restrict__ col,
                             const int* __restrict__ batch, float* __restrict__ out) {
    __shared__ float sm[NGRAPH];
    if (threadIdx.x < NGRAPH) sm[threadIdx.x] = 0.f;
    __syncthreads();
    for (int e = blockIdx.x * blockDim.x + threadIdx.x; e < N_EDGES;
         e += gridDim.x * blockDim.x) {
        int r = row[e];
        atomicAdd(&sm[batch[r]], 0.5f * d_probs[r] * d_probs[col[e]]);
    }
    __syncthreads();
    if (threadIdx.x < NGRAPH) atomicAdd(&out[threadIdx.x], sm[threadIdx.x]);
}

// ---------------- launch ----------------
extern "C" void kernel_launch(void* const* d_in, const int* in_sizes, int n_in,
                              void* d_out, int out_size)
{
    const float* x     = (const float*)d_in[0];
    const int*   ei    = (const int*)d_in[1];
    const int*   batch = (const int*)d_in[2];
    const float* W_gcn = (const float*)d_in[3];
    const float* b_gcn = (const float*)d_in[4];
    const float* W_gg  = (const float*)d_in[5];
    const float* W_ih  = (const float*)d_in[6];
    const float* W_hh  = (const float*)d_in[7];
    const float* b_ih  = (const float*)d_in[8];
    const float* b_hh  = (const float*)d_in[9];
    const float* W1    = (const float*)d_in[10];
    const float* b1    = (const float*)d_in[11];
    const float* W2    = (const float*)d_in[12];
    const float* b2    = (const float*)d_in[13];
    float* out = (float*)d_out;
    const int* row = ei;
    const int* col = ei + N_EDGES;

    const int SMEM = 2 * 36864;    // k_mm
    const int SMG  = 2 * 64512;    // k_gates
    cudaFuncSetAttribute(k_mm<0>, cudaFuncAttributeMaxDynamicSharedMemorySize, SMEM);
    cudaFuncSetAttribute(k_mm<1>, cudaFuncAttributeMaxDynamicSharedMemorySize, SMEM);
    cudaFuncSetAttribute(k_gates, cudaFuncAttributeMaxDynamicSharedMemorySize, SMG);

    __half *xh, *gh, *mh, *hh, *wh, *XWh;
    float *XW, *Gb;
    cudaGetSymbolAddress((void**)&xh, d_xh);
    cudaGetSymbolAddress((void**)&gh, d_gh);
    cudaGetSymbolAddress((void**)&mh, d_mh);
    cudaGetSymbolAddress((void**)&hh, d_hh);
    cudaGetSymbolAddress((void**)&wh, d_wh);
    cudaGetSymbolAddress((void**)&XWh, d_XWh);
    cudaGetSymbolAddress((void**)&XW, d_XW);
    cudaGetSymbolAddress((void**)&Gb, d_Gb);

    // CSR build + weight prep
    k_zero<<<196, 256>>>(out);
    k_count<<<3125, 256>>>(row, col);
    k_dinv<<<196, 256>>>();
    k_scan1<<<196, 256>>>();
    k_scan2<<<1, 256>>>();
    k_scan3<<<196, 256>>>();
    k_scatter<<<3125, 256>>>(row, col);
    k_quant_x<<<6250, 256>>>(x);
    k_wq<<<320, 256>>>(W_gcn, W_hh, W1);
    k_wc<<<1152, 128>>>(W_gg, W_ih);

    // GCN
    k_mm<0><<<MTILES, 256, SMEM>>>(xh, wh, nullptr, XWh);
    k_gcn_agg<<<6250, 256>>>(b_gcn);

    // 3x GatedGraphConv (W_gg folded into gates GEMM)
    for (int l = 0; l < 3; l++) {
        k_gg_agg<<<6250, 256>>>();
        k_gates<<<782, 512, SMG>>>(mh, gh, wh + (long)(128 + l * 384) * 128,
                                   wh + 1280L * 128, b_ih, b_hh, Gb);
    }

    // head
    k_resid<<<6250, 256>>>();
    k_mm<1><<<MTILES, 256, SMEM>>>(hh, wh + 1664L * 128, b1, XW);
    k_probs<<<6250, 256>>>(W2, b2);

    // loss
    k_loss_nodes<<<512, 256>>>(batch, out);
    k_loss_edges<<<512, 256>>>(row, col, batch, out);
}